// round 1
// baseline (speedup 1.0000x reference)
#include <cuda_runtime.h>
#include <math.h>

#define BB   256   // batch
#define LL   1024  // enc length
#define DD   256   // ENC_D
#define HH   256   // DEC_H
#define EMBD 128
#define NOUT 172
#define KIN  640   // EMB + DEC_H(o_t) + DEC_H(h0)
#define NCH  8     // L / BMA

// scratch (device globals; no allocation allowed)
__device__ float g_A[BB * KIN];
__device__ float g_gates[BB * 4 * HH];
__device__ float g_hp[BB * DD];
__device__ float g_ctx[BB * DD];
__device__ float g_partS[BB * NCH];
__device__ float g_partC[BB * NCH * DD];

__device__ __forceinline__ float tanh_fast(float x) {
    float y;
    asm("tanh.approx.f32 %0, %1;" : "=f"(y) : "f"(x));
    return y;
}
__device__ __forceinline__ float sigmoidf(float x) {
    return 1.0f / (1.0f + expf(-x));
}

// ---------------------------------------------------------------------------
// 1) Build LSTM input rows: A[b] = [emb[lasttarget[b]] | o_t[b] | h0[b]]
// ---------------------------------------------------------------------------
__global__ void prep_A_kernel(const float* __restrict__ emb,
                              const int* __restrict__ lt,
                              const float* __restrict__ o_t,
                              const float* __restrict__ h0) {
    int b = blockIdx.x;
    int k = threadIdx.x;  // 640 threads
    float v;
    if (k < EMBD)       v = emb[lt[b] * EMBD + k];
    else if (k < 384)   v = o_t[b * HH + (k - EMBD)];
    else                v = h0[b * HH + (k - 384)];
    g_A[b * KIN + k] = v;
}

// ---------------------------------------------------------------------------
// 2) gates = A @ [W_ih|W_hh]^T + b_ih + b_hh   (256 x 1024, K=640)
//    tiled GEMM: BM=64, BN=64, BK=32, 256 thr, 4x4 microtile
// ---------------------------------------------------------------------------
__global__ __launch_bounds__(256) void gates_gemm_kernel(
    const float* __restrict__ W_ih, const float* __restrict__ W_hh,
    const float* __restrict__ b_ih, const float* __restrict__ b_hh) {
    __shared__ float aT[32 * 65];  // [kk][r]
    __shared__ float bS[32 * 65];  // [kk][j]
    int n0 = blockIdx.x * 64;
    int m0 = blockIdx.y * 64;
    int tid = threadIdx.x;
    int tx = tid & 15, ty = tid >> 4;

    float acc[4][4];
#pragma unroll
    for (int i = 0; i < 4; i++)
#pragma unroll
        for (int j = 0; j < 4; j++) acc[i][j] = 0.f;

    for (int k0 = 0; k0 < KIN; k0 += 32) {
        __syncthreads();
#pragma unroll
        for (int rep = 0; rep < 8; rep++) {
            int idx = rep * 256 + tid;
            int r = idx >> 5, kk = idx & 31;
            aT[kk * 65 + r] = g_A[(m0 + r) * KIN + k0 + kk];
        }
#pragma unroll
        for (int rep = 0; rep < 8; rep++) {
            int idx = rep * 256 + tid;
            int j = idx >> 5, kk = idx & 31;
            int kg = k0 + kk;
            int jg = n0 + j;
            float v = (kg < 384) ? W_ih[jg * 384 + kg]
                                 : W_hh[jg * 256 + (kg - 384)];
            bS[kk * 65 + j] = v;
        }
        __syncthreads();
#pragma unroll
        for (int kk = 0; kk < 32; kk++) {
            float a[4], w[4];
#pragma unroll
            for (int i = 0; i < 4; i++) a[i] = aT[kk * 65 + ty * 4 + i];
#pragma unroll
            for (int j = 0; j < 4; j++) w[j] = bS[kk * 65 + tx * 4 + j];
#pragma unroll
            for (int i = 0; i < 4; i++)
#pragma unroll
                for (int j = 0; j < 4; j++) acc[i][j] += a[i] * w[j];
        }
    }
#pragma unroll
    for (int i = 0; i < 4; i++) {
        int row = m0 + ty * 4 + i;
#pragma unroll
        for (int j = 0; j < 4; j++) {
            int col = n0 + tx * 4 + j;
            g_gates[row * 1024 + col] = acc[i][j] + b_ih[col] + b_hh[col];
        }
    }
}

// ---------------------------------------------------------------------------
// 3) LSTM cell update -> h_t, c_t into d_out
// ---------------------------------------------------------------------------
__global__ void cell_kernel(const float* __restrict__ c0, float* __restrict__ out) {
    int b = blockIdx.x, d = threadIdx.x;
    const float* g = g_gates + b * 1024;
    float ig = g[d], fg = g[256 + d], gg = g[512 + d], og = g[768 + d];
    float c = sigmoidf(fg) * c0[b * HH + d] + sigmoidf(ig) * tanhf(gg);
    float h = sigmoidf(og) * tanhf(c);
    out[b * HH + d] = h;                 // h_t
    out[BB * HH + b * HH + d] = c;       // c_t
}

// ---------------------------------------------------------------------------
// 4) hp = h_t @ W2^T  (256x256, K=256)
// ---------------------------------------------------------------------------
__global__ void hproj_kernel(const float* __restrict__ W2, const float* __restrict__ out) {
    __shared__ float hrow[HH];
    int b = blockIdx.x, d = threadIdx.x;
    hrow[d] = out[b * HH + d];
    __syncthreads();
    float acc = 0.f;
    const float* w = W2 + d * HH;
#pragma unroll 8
    for (int k = 0; k < HH; k++) acc += hrow[k] * w[k];
    g_hp[b * DD + d] = acc;
}

// ---------------------------------------------------------------------------
// 5) Fused attention pass: alpha = tanh(enc@W1^T + hp), s = beta.alpha,
//    w = exp(s) (max-free: |s| is tiny), partial sums of w and w*enc.
//    BM=128 L-rows per block, BN=64 x 4 tiles over D, BK=32, 8x4 microtile.
// ---------------------------------------------------------------------------
__global__ __launch_bounds__(256, 2) void attn_kernel(
    const float* __restrict__ enc, const float* __restrict__ W1,
    const float* __restrict__ beta) {
    __shared__ float aT[32 * 129];   // [kk][r], r<128
    __shared__ float w1S[32 * 65];   // [kk][j], j<64
    __shared__ float hpS[DD];
    __shared__ float betaS[DD];
    __shared__ float sred[128 * 17];
    __shared__ float wS[128];

    int b = blockIdx.y;
    int l0 = blockIdx.x * 128;
    int tid = threadIdx.x;
    int tx = tid & 15, ty = tid >> 4;

    hpS[tid] = g_hp[b * DD + tid];
    betaS[tid] = beta[tid];

    float srow[8];
#pragma unroll
    for (int i = 0; i < 8; i++) srow[i] = 0.f;

    const float* encB = enc + ((size_t)b * LL + l0) * DD;

    for (int nt = 0; nt < 4; nt++) {
        int n0 = nt * 64;
        float acc[8][4];
#pragma unroll
        for (int i = 0; i < 8; i++)
#pragma unroll
            for (int j = 0; j < 4; j++) acc[i][j] = 0.f;

        for (int k0 = 0; k0 < DD; k0 += 32) {
            __syncthreads();
#pragma unroll
            for (int rep = 0; rep < 16; rep++) {
                int idx = rep * 256 + tid;
                int r = idx >> 5, kk = idx & 31;
                aT[kk * 129 + r] = encB[r * DD + k0 + kk];
            }
#pragma unroll
            for (int rep = 0; rep < 8; rep++) {
                int idx = rep * 256 + tid;
                int j = idx >> 5, kk = idx & 31;
                w1S[kk * 65 + j] = W1[(n0 + j) * DD + k0 + kk];
            }
            __syncthreads();
#pragma unroll
            for (int kk = 0; kk < 32; kk++) {
                float a[8], w[4];
#pragma unroll
                for (int i = 0; i < 8; i++) a[i] = aT[kk * 129 + ty * 8 + i];
#pragma unroll
                for (int j = 0; j < 4; j++) w[j] = w1S[kk * 65 + tx * 4 + j];
#pragma unroll
                for (int i = 0; i < 8; i++)
#pragma unroll
                    for (int j = 0; j < 4; j++) acc[i][j] += a[i] * w[j];
            }
        }
        // epilogue: srow += beta_d * tanh(acc + hp_d)
#pragma unroll
        for (int j = 0; j < 4; j++) {
            int c = n0 + tx * 4 + j;
            float bet = betaS[c], hpv = hpS[c];
#pragma unroll
            for (int i = 0; i < 8; i++)
                srow[i] += bet * tanh_fast(acc[i][j] + hpv);
        }
    }

    // reduce scores across tx
#pragma unroll
    for (int i = 0; i < 8; i++) sred[(ty * 8 + i) * 17 + tx] = srow[i];
    __syncthreads();
    if (tid < 128) {
        float s = 0.f;
#pragma unroll
        for (int t = 0; t < 16; t++) s += sred[tid * 17 + t];
        wS[tid] = expf(s);
    }
    __syncthreads();

    if (tid < 32) {
        float ps = wS[tid] + wS[tid + 32] + wS[tid + 64] + wS[tid + 96];
#pragma unroll
        for (int o = 16; o > 0; o >>= 1) ps += __shfl_down_sync(0xffffffffu, ps, o);
        if (tid == 0) g_partS[b * NCH + blockIdx.x] = ps;
    }

    // partial context: C[d] = sum_l w_l * enc[l][d]   (enc tile is L2-hot)
    float C = 0.f;
    for (int l = 0; l < 128; l++) C += wS[l] * encB[l * DD + tid];
    g_partC[(b * NCH + blockIdx.x) * DD + tid] = C;
}

// ---------------------------------------------------------------------------
// 6) context = sum(partC) / sum(partS)
// ---------------------------------------------------------------------------
__global__ void ctx_reduce_kernel() {
    int b = blockIdx.x, d = threadIdx.x;
    float S = 0.f, C = 0.f;
#pragma unroll
    for (int c = 0; c < NCH; c++) {
        S += g_partS[b * NCH + c];
        C += g_partC[(b * NCH + c) * DD + d];
    }
    g_ctx[b * DD + d] = C / S;
}

// ---------------------------------------------------------------------------
// 7) o_new = tanh([h_t | context] @ W3^T)  (K=512)
// ---------------------------------------------------------------------------
__global__ void onew_kernel(const float* __restrict__ W3, float* __restrict__ out) {
    __shared__ float cat[2 * HH];
    int b = blockIdx.x, d = threadIdx.x;
    cat[d] = out[b * HH + d];            // h_t
    cat[HH + d] = g_ctx[b * DD + d];     // context
    __syncthreads();
    float acc = 0.f;
    const float* w = W3 + d * (2 * HH);
#pragma unroll 8
    for (int k = 0; k < 2 * HH; k++) acc += cat[k] * w[k];
    out[2 * BB * HH + b * HH + d] = tanhf(acc);
}

// ---------------------------------------------------------------------------
// 8) logit = softmax(o_new @ W_out^T)  (256 x 172, K=256)
// ---------------------------------------------------------------------------
__global__ void logit_kernel(const float* __restrict__ Wout, float* __restrict__ out) {
    __shared__ float orow[HH];
    __shared__ float lg[NOUT];
    __shared__ float red[2];
    int b = blockIdx.x, t = threadIdx.x;
    orow[t] = out[2 * BB * HH + b * HH + t];
    __syncthreads();
    if (t < NOUT) {
        float acc = 0.f;
        const float* w = Wout + t * HH;
#pragma unroll 8
        for (int k = 0; k < HH; k++) acc += orow[k] * w[k];
        lg[t] = acc;
    }
    __syncthreads();
    if (t == 0) {
        float m = lg[0];
        for (int i = 1; i < NOUT; i++) m = fmaxf(m, lg[i]);
        red[0] = m;
    }
    __syncthreads();
    if (t < NOUT) lg[t] = expf(lg[t] - red[0]);
    __syncthreads();
    if (t == 0) {
        float s = 0.f;
        for (int i = 0; i < NOUT; i++) s += lg[i];
        red[1] = s;
    }
    __syncthreads();
    if (t < NOUT) out[3 * BB * HH + b * NOUT + t] = lg[t] / red[1];
}

// ---------------------------------------------------------------------------
extern "C" void kernel_launch(void* const* d_in, const int* in_sizes, int n_in,
                              void* d_out, int out_size) {
    const float* h0      = (const float*)d_in[0];
    const float* c0      = (const float*)d_in[1];
    const float* o_t     = (const float*)d_in[2];
    const float* enc_out = (const float*)d_in[3];
    const int*   lt      = (const int*)  d_in[4];
    const float* emb     = (const float*)d_in[5];
    const float* W_ih    = (const float*)d_in[6];
    const float* W_hh    = (const float*)d_in[7];
    const float* b_ih    = (const float*)d_in[8];
    const float* b_hh    = (const float*)d_in[9];
    const float* W1      = (const float*)d_in[10];
    const float* W2      = (const float*)d_in[11];
    const float* W3      = (const float*)d_in[12];
    const float* W_out   = (const float*)d_in[13];
    const float* beta    = (const float*)d_in[14];
    float* out = (float*)d_out;

    prep_A_kernel<<<BB, KIN>>>(emb, lt, o_t, h0);
    gates_gemm_kernel<<<dim3(16, 4), 256>>>(W_ih, W_hh, b_ih, b_hh);
    cell_kernel<<<BB, HH>>>(c0, out);
    hproj_kernel<<<BB, DD>>>(W2, out);
    attn_kernel<<<dim3(NCH, BB), 256>>>(enc_out, W1, beta);
    ctx_reduce_kernel<<<BB, DD>>>();
    onew_kernel<<<BB, HH>>>(W3, out);
    logit_kernel<<<BB, 256>>>(W_out, out);
}

// round 3
// speedup vs baseline: 2.6357x; 2.6357x over previous
#include <cuda_runtime.h>
#include <cuda_bf16.h>
#include <math.h>
#include <cstdint>

#define BB   256   // batch
#define LL   1024  // enc length
#define DD   256   // ENC_D
#define HH   256   // DEC_H
#define EMBD 128
#define NOUT 172
#define KIN  640   // EMB + DEC_H(o_t) + DEC_H(h0)
#define NCH  8     // L / 128

// ---------------- scratch (device globals; no allocation allowed) ----------
__device__ float g_A[BB * KIN];
__device__ float g_gates[BB * 4 * HH];
__device__ float g_hp[BB * DD];
__device__ float g_ctx[BB * DD];
__device__ float g_partS[BB * NCH];
__device__ float g_partC[BB * NCH * DD];
__device__ float g_logits[BB * NOUT];
__device__ uint32_t g_W1bf[256 * 132];   // W1 bf16, padded rows of 132 u32 (264 bf16)

// ---------------- helpers ---------------------------------------------------
__device__ __forceinline__ float tanh_fast(float x) {
    float y;
    asm("tanh.approx.f32 %0, %1;" : "=f"(y) : "f"(x));
    return y;
}
__device__ __forceinline__ float sigmoidf(float x) {
    return 1.0f / (1.0f + expf(-x));
}
__device__ __forceinline__ void mma_bf16(float* c, const uint32_t* a, const uint32_t* b) {
    asm volatile(
        "mma.sync.aligned.m16n8k16.row.col.f32.bf16.bf16.f32 "
        "{%0,%1,%2,%3}, {%4,%5,%6,%7}, {%8,%9}, {%0,%1,%2,%3};"
        : "+f"(c[0]), "+f"(c[1]), "+f"(c[2]), "+f"(c[3])
        : "r"(a[0]), "r"(a[1]), "r"(a[2]), "r"(a[3]), "r"(b[0]), "r"(b[1]));
}

// attn smem layout (bytes)
#define ROWB   528                   // 264 bf16 per padded row
#define SM_HP    0                   // 256 f32
#define SM_BETA  1024                // 256 f32
#define SM_WSOFF 2048                // 128 f32
#define SM_ENC   4096                // 128 x 528 B = 67584
#define SM_W1    (4096 + 128 * ROWB) // 256 x 528 B = 135168
#define SM_TOTAL (SM_W1 + 256 * ROWB)

// ---------------------------------------------------------------------------
// 1) Build LSTM input rows: A[b] = [emb[lasttarget[b]] | o_t[b] | h0[b]]
// ---------------------------------------------------------------------------
__global__ void prep_A_kernel(const float* __restrict__ emb,
                              const int* __restrict__ lt,
                              const float* __restrict__ o_t,
                              const float* __restrict__ h0) {
    int b = blockIdx.x;
    int k = threadIdx.x;
    float v;
    if (k < EMBD)       v = emb[lt[b] * EMBD + k];
    else if (k < 384)   v = o_t[b * HH + (k - EMBD)];
    else                v = h0[b * HH + (k - 384)];
    g_A[b * KIN + k] = v;
}

// ---------------------------------------------------------------------------
// 1b) Pre-pack W1 -> bf16, padded row-major [256][264]
// ---------------------------------------------------------------------------
__global__ void prep_W1_kernel(const float* __restrict__ W1) {
    int n = blockIdx.x;           // 256 rows
    int kp = threadIdx.x;         // 128 pairs
    __nv_bfloat162 h = __floats2bfloat162_rn(W1[n * DD + 2 * kp], W1[n * DD + 2 * kp + 1]);
    g_W1bf[n * 132 + kp] = *(uint32_t*)&h;
    if (kp < 4) g_W1bf[n * 132 + 128 + kp] = 0u;   // zero padding
}

// ---------------------------------------------------------------------------
// 2) gates = A @ [W_ih|W_hh]^T + b_ih + b_hh   (256 x 1024, K=640)
// ---------------------------------------------------------------------------
__global__ __launch_bounds__(256) void gates_gemm_kernel(
    const float* __restrict__ W_ih, const float* __restrict__ W_hh,
    const float* __restrict__ b_ih, const float* __restrict__ b_hh) {
    __shared__ float aT[32 * 65];
    __shared__ float bS[32 * 65];
    int n0 = blockIdx.x * 64;
    int m0 = blockIdx.y * 64;
    int tid = threadIdx.x;
    int tx = tid & 15, ty = tid >> 4;

    float acc[4][4];
#pragma unroll
    for (int i = 0; i < 4; i++)
#pragma unroll
        for (int j = 0; j < 4; j++) acc[i][j] = 0.f;

    for (int k0 = 0; k0 < KIN; k0 += 32) {
        __syncthreads();
#pragma unroll
        for (int rep = 0; rep < 8; rep++) {
            int idx = rep * 256 + tid;
            int r = idx >> 5, kk = idx & 31;
            aT[kk * 65 + r] = g_A[(m0 + r) * KIN + k0 + kk];
        }
#pragma unroll
        for (int rep = 0; rep < 8; rep++) {
            int idx = rep * 256 + tid;
            int j = idx >> 5, kk = idx & 31;
            int kg = k0 + kk;
            int jg = n0 + j;
            bS[kk * 65 + j] = (kg < 384) ? W_ih[jg * 384 + kg] : W_hh[jg * 256 + (kg - 384)];
        }
        __syncthreads();
#pragma unroll
        for (int kk = 0; kk < 32; kk++) {
            float a[4], w[4];
#pragma unroll
            for (int i = 0; i < 4; i++) a[i] = aT[kk * 65 + ty * 4 + i];
#pragma unroll
            for (int j = 0; j < 4; j++) w[j] = bS[kk * 65 + tx * 4 + j];
#pragma unroll
            for (int i = 0; i < 4; i++)
#pragma unroll
                for (int j = 0; j < 4; j++) acc[i][j] += a[i] * w[j];
        }
    }
#pragma unroll
    for (int i = 0; i < 4; i++) {
        int row = m0 + ty * 4 + i;
#pragma unroll
        for (int j = 0; j < 4; j++) {
            int col = n0 + tx * 4 + j;
            g_gates[row * 1024 + col] = acc[i][j] + b_ih[col] + b_hh[col];
        }
    }
}

// ---------------------------------------------------------------------------
// 3) LSTM cell -> h_t, c_t
// ---------------------------------------------------------------------------
__global__ void cell_kernel(const float* __restrict__ c0, float* __restrict__ out) {
    int b = blockIdx.x, d = threadIdx.x;
    const float* g = g_gates + b * 1024;
    float ig = g[d], fg = g[256 + d], gg = g[512 + d], og = g[768 + d];
    float c = sigmoidf(fg) * c0[b * HH + d] + sigmoidf(ig) * tanhf(gg);
    float h = sigmoidf(og) * tanhf(c);
    out[b * HH + d] = h;
    out[BB * HH + b * HH + d] = c;
}

// ---------------------------------------------------------------------------
// 4) hp = h_t @ W2^T  (256x256, K=256) — tiled GEMM
// ---------------------------------------------------------------------------
__global__ __launch_bounds__(256) void hproj_gemm_kernel(
    const float* __restrict__ W2, const float* __restrict__ out) {
    __shared__ float aT[32 * 65];
    __shared__ float bS[32 * 65];
    int n0 = blockIdx.x * 64;
    int m0 = blockIdx.y * 64;
    int tid = threadIdx.x;
    int tx = tid & 15, ty = tid >> 4;

    float acc[4][4];
#pragma unroll
    for (int i = 0; i < 4; i++)
#pragma unroll
        for (int j = 0; j < 4; j++) acc[i][j] = 0.f;

    for (int k0 = 0; k0 < HH; k0 += 32) {
        __syncthreads();
#pragma unroll
        for (int rep = 0; rep < 8; rep++) {
            int idx = rep * 256 + tid;
            int r = idx >> 5, kk = idx & 31;
            aT[kk * 65 + r] = out[(m0 + r) * HH + k0 + kk];
        }
#pragma unroll
        for (int rep = 0; rep < 8; rep++) {
            int idx = rep * 256 + tid;
            int j = idx >> 5, kk = idx & 31;
            bS[kk * 65 + j] = W2[(n0 + j) * HH + k0 + kk];
        }
        __syncthreads();
#pragma unroll
        for (int kk = 0; kk < 32; kk++) {
            float a[4], w[4];
#pragma unroll
            for (int i = 0; i < 4; i++) a[i] = aT[kk * 65 + ty * 4 + i];
#pragma unroll
            for (int j = 0; j < 4; j++) w[j] = bS[kk * 65 + tx * 4 + j];
#pragma unroll
            for (int i = 0; i < 4; i++)
#pragma unroll
                for (int j = 0; j < 4; j++) acc[i][j] += a[i] * w[j];
        }
    }
#pragma unroll
    for (int i = 0; i < 4; i++)
#pragma unroll
        for (int j = 0; j < 4; j++)
            g_hp[(m0 + ty * 4 + i) * DD + n0 + tx * 4 + j] = acc[i][j];
}

// ---------------------------------------------------------------------------
// 5) Attention via mma.sync bf16 (HMMA):
//    D(128x256) = enc_tile @ W1^T; s = beta . tanh(D + hp); w = exp(s);
//    partial S and context per 128-row l-tile.
//    8 warps x 16 rows; N in 4 chunks of 64; K=256 fully staged in SMEM.
// ---------------------------------------------------------------------------
__global__ __launch_bounds__(256) void attn_mma_kernel(
    const float* __restrict__ enc, const float* __restrict__ beta) {
    extern __shared__ char sm[];
    float* hpS   = (float*)(sm + SM_HP);
    float* betaS = (float*)(sm + SM_BETA);
    float* wS    = (float*)(sm + SM_WSOFF);
    char*  encS  = sm + SM_ENC;
    char*  w1S   = sm + SM_W1;

    int tid = threadIdx.x, wid = tid >> 5, lane = tid & 31;
    int b = blockIdx.y, l0 = blockIdx.x * 128;

    hpS[tid] = g_hp[b * DD + tid];
    betaS[tid] = beta[tid];

    // W1 bf16 -> smem: 135168 B = 8448 uint4, 33 iters x 256 thr
    {
        const uint4* src = (const uint4*)g_W1bf;
        uint4* dst = (uint4*)w1S;
#pragma unroll 4
        for (int it = 0; it < 33; it++) dst[it * 256 + tid] = src[it * 256 + tid];
    }

    // enc tile fp32 -> bf16 padded smem rows (128 x 256, row stride 528 B)
    const float* encB = enc + ((size_t)b * LL + l0) * DD;
#pragma unroll 4
    for (int it = 0; it < 32; it++) {
        int idx = it * 256 + tid;       // float4 index (8192 total)
        int r = idx >> 6;
        int c = (idx & 63) * 4;
        float4 v = *(const float4*)(encB + r * DD + c);
        __nv_bfloat162 p0 = __floats2bfloat162_rn(v.x, v.y);
        __nv_bfloat162 p1 = __floats2bfloat162_rn(v.z, v.w);
        uint2 u;
        u.x = *(uint32_t*)&p0;
        u.y = *(uint32_t*)&p1;
        *(uint2*)(encS + r * ROWB + c * 2) = u;
    }
    __syncthreads();

    int m0 = wid * 16;
    int g = lane >> 2, t = lane & 3;
    const char* arow = encS + (m0 + g) * ROWB + t * 4;
    float s0 = 0.f, s1 = 0.f;

#pragma unroll
    for (int nch = 0; nch < 4; nch++) {
        int n0 = nch * 64;
        float acc[8][4];
#pragma unroll
        for (int j = 0; j < 8; j++)
#pragma unroll
            for (int i = 0; i < 4; i++) acc[j][i] = 0.f;

#pragma unroll
        for (int kb = 0; kb < 16; kb++) {
            const char* pa = arow + kb * 32;
            uint32_t a[4];
            a[0] = *(const uint32_t*)(pa);
            a[1] = *(const uint32_t*)(pa + 8 * ROWB);
            a[2] = *(const uint32_t*)(pa + 16);
            a[3] = *(const uint32_t*)(pa + 8 * ROWB + 16);
#pragma unroll
            for (int jt = 0; jt < 8; jt++) {
                const char* pb = w1S + (n0 + jt * 8 + g) * ROWB + t * 4 + kb * 32;
                uint32_t bf[2];
                bf[0] = *(const uint32_t*)(pb);
                bf[1] = *(const uint32_t*)(pb + 16);
                mma_bf16(acc[jt], a, bf);
            }
        }
        // fused epilogue: s += beta_c * tanh(acc + hp_c)
#pragma unroll
        for (int jt = 0; jt < 8; jt++) {
            int c = n0 + jt * 8 + t * 2;
            float b0 = betaS[c], b1 = betaS[c + 1];
            float h0v = hpS[c], h1v = hpS[c + 1];
            s0 += b0 * tanh_fast(acc[jt][0] + h0v) + b1 * tanh_fast(acc[jt][1] + h1v);
            s1 += b0 * tanh_fast(acc[jt][2] + h0v) + b1 * tanh_fast(acc[jt][3] + h1v);
        }
    }
    // reduce across the quad (lanes sharing the same row)
    s0 += __shfl_xor_sync(0xffffffffu, s0, 1);
    s0 += __shfl_xor_sync(0xffffffffu, s0, 2);
    s1 += __shfl_xor_sync(0xffffffffu, s1, 1);
    s1 += __shfl_xor_sync(0xffffffffu, s1, 2);
    if (t == 0) {
        wS[m0 + g] = expf(s0);
        wS[m0 + g + 8] = expf(s1);
    }
    __syncthreads();

    if (tid < 32) {
        float ps = wS[tid] + wS[tid + 32] + wS[tid + 64] + wS[tid + 96];
#pragma unroll
        for (int o = 16; o > 0; o >>= 1) ps += __shfl_down_sync(0xffffffffu, ps, o);
        if (tid == 0) g_partS[b * NCH + blockIdx.x] = ps;
    }

    // partial context from gmem fp32 (tile is L2-hot)
    float C = 0.f;
#pragma unroll 4
    for (int l = 0; l < 128; l++) C += wS[l] * encB[l * DD + tid];
    g_partC[(b * NCH + blockIdx.x) * DD + tid] = C;
}

// ---------------------------------------------------------------------------
// 6) context = sum(partC) / sum(partS)
// ---------------------------------------------------------------------------
__global__ void ctx_reduce_kernel() {
    int b = blockIdx.x, d = threadIdx.x;
    float S = 0.f, C = 0.f;
#pragma unroll
    for (int c = 0; c < NCH; c++) {
        S += g_partS[b * NCH + c];
        C += g_partC[(b * NCH + c) * DD + d];
    }
    g_ctx[b * DD + d] = C / S;
}

// ---------------------------------------------------------------------------
// 7) o_new = tanh([h_t | context] @ W3^T)  (256x256, K=512) — tiled
// ---------------------------------------------------------------------------
__global__ __launch_bounds__(256) void onew_gemm_kernel(
    const float* __restrict__ W3, float* __restrict__ out) {
    __shared__ float aT[32 * 65];
    __shared__ float bS[32 * 65];
    int n0 = blockIdx.x * 64;
    int m0 = blockIdx.y * 64;
    int tid = threadIdx.x;
    int tx = tid & 15, ty = tid >> 4;

    float acc[4][4];
#pragma unroll
    for (int i = 0; i < 4; i++)
#pragma unroll
        for (int j = 0; j < 4; j++) acc[i][j] = 0.f;

    for (int k0 = 0; k0 < 512; k0 += 32) {
        __syncthreads();
#pragma unroll
        for (int rep = 0; rep < 8; rep++) {
            int idx = rep * 256 + tid;
            int r = idx >> 5, kk = idx & 31;
            int kg = k0 + kk;
            aT[kk * 65 + r] = (kg < 256) ? out[(m0 + r) * HH + kg]
                                         : g_ctx[(m0 + r) * DD + (kg - 256)];
        }
#pragma unroll
        for (int rep = 0; rep < 8; rep++) {
            int idx = rep * 256 + tid;
            int j = idx >> 5, kk = idx & 31;
            bS[kk * 65 + j] = W3[(n0 + j) * 512 + k0 + kk];
        }
        __syncthreads();
#pragma unroll
        for (int kk = 0; kk < 32; kk++) {
            float a[4], w[4];
#pragma unroll
            for (int i = 0; i < 4; i++) a[i] = aT[kk * 65 + ty * 4 + i];
#pragma unroll
            for (int j = 0; j < 4; j++) w[j] = bS[kk * 65 + tx * 4 + j];
#pragma unroll
            for (int i = 0; i < 4; i++)
#pragma unroll
                for (int j = 0; j < 4; j++) acc[i][j] += a[i] * w[j];
        }
    }
#pragma unroll
    for (int i = 0; i < 4; i++)
#pragma unroll
        for (int j = 0; j < 4; j++)
            out[2 * BB * HH + (m0 + ty * 4 + i) * HH + n0 + tx * 4 + j] = tanhf(acc[i][j]);
}

// ---------------------------------------------------------------------------
// 8) raw logits = o_new @ W_out^T  (256x172, K=256) — tiled
// ---------------------------------------------------------------------------
__global__ __launch_bounds__(256) void logit_gemm_kernel(
    const float* __restrict__ Wout, const float* __restrict__ out) {
    __shared__ float aT[32 * 65];
    __shared__ float bS[32 * 65];
    int n0 = blockIdx.x * 64;
    int m0 = blockIdx.y * 64;
    int tid = threadIdx.x;
    int tx = tid & 15, ty = tid >> 4;
    const float* onew = out + 2 * BB * HH;

    float acc[4][4];
#pragma unroll
    for (int i = 0; i < 4; i++)
#pragma unroll
        for (int j = 0; j < 4; j++) acc[i][j] = 0.f;

    for (int k0 = 0; k0 < HH; k0 += 32) {
        __syncthreads();
#pragma unroll
        for (int rep = 0; rep < 8; rep++) {
            int idx = rep * 256 + tid;
            int r = idx >> 5, kk = idx & 31;
            aT[kk * 65 + r] = onew[(m0 + r) * HH + k0 + kk];
        }
#pragma unroll
        for (int rep = 0; rep < 8; rep++) {
            int idx = rep * 256 + tid;
            int j = idx >> 5, kk = idx & 31;
            int jg = n0 + j;
            bS[kk * 65 + j] = (jg < NOUT) ? Wout[jg * HH + k0 + kk] : 0.f;
        }
        __syncthreads();
#pragma unroll
        for (int kk = 0; kk < 32; kk++) {
            float a[4], w[4];
#pragma unroll
            for (int i = 0; i < 4; i++) a[i] = aT[kk * 65 + ty * 4 + i];
#pragma unroll
            for (int j = 0; j < 4; j++) w[j] = bS[kk * 65 + tx * 4 + j];
#pragma unroll
            for (int i = 0; i < 4; i++)
#pragma unroll
                for (int j = 0; j < 4; j++) acc[i][j] += a[i] * w[j];
        }
    }
#pragma unroll
    for (int i = 0; i < 4; i++) {
        int row = m0 + ty * 4 + i;
#pragma unroll
        for (int j = 0; j < 4; j++) {
            int col = n0 + tx * 4 + j;
            if (col < NOUT) g_logits[row * NOUT + col] = acc[i][j];
        }
    }
}

// ---------------------------------------------------------------------------
// 9) logit softmax
// ---------------------------------------------------------------------------
__global__ void softmax_logit_kernel(float* __restrict__ out) {
    __shared__ float lg[NOUT];
    __shared__ float red;
    int b = blockIdx.x, t = threadIdx.x;
    if (t < NOUT) lg[t] = g_logits[b * NOUT + t];
    __syncthreads();
    if (t == 0) {
        float m = lg[0];
        for (int i = 1; i < NOUT; i++) m = fmaxf(m, lg[i]);
        red = m;
    }
    __syncthreads();
    float e = (t < NOUT) ? expf(lg[t] - red) : 0.f;
    __syncthreads();
    if (t < NOUT) lg[t] = e;
    __syncthreads();
    if (t == 0) {
        float s = 0.f;
        for (int i = 0; i < NOUT; i++) s += lg[i];
        red = s;
    }
    __syncthreads();
    if (t < NOUT) out[3 * BB * HH + b * NOUT + t] = lg[t] / red;
}

// ---------------------------------------------------------------------------
extern "C" void kernel_launch(void* const* d_in, const int* in_sizes, int n_in,
                              void* d_out, int out_size) {
    const float* h0      = (const float*)d_in[0];
    const float* c0      = (const float*)d_in[1];
    const float* o_t     = (const float*)d_in[2];
    const float* enc_out = (const float*)d_in[3];
    const int*   lt      = (const int*)  d_in[4];
    const float* emb     = (const float*)d_in[5];
    const float* W_ih    = (const float*)d_in[6];
    const float* W_hh    = (const float*)d_in[7];
    const float* b_ih    = (const float*)d_in[8];
    const float* b_hh    = (const float*)d_in[9];
    const float* W1      = (const float*)d_in[10];
    const float* W2      = (const float*)d_in[11];
    const float* W3      = (const float*)d_in[12];
    const float* W_out   = (const float*)d_in[13];
    const float* beta    = (const float*)d_in[14];
    float* out = (float*)d_out;

    cudaFuncSetAttribute(attn_mma_kernel, cudaFuncAttributeMaxDynamicSharedMemorySize, SM_TOTAL);

    prep_A_kernel<<<BB, KIN>>>(emb, lt, o_t, h0);
    prep_W1_kernel<<<256, 128>>>(W1);
    gates_gemm_kernel<<<dim3(16, 4), 256>>>(W_ih, W_hh, b_ih, b_hh);
    cell_kernel<<<BB, HH>>>(c0, out);
    hproj_gemm_kernel<<<dim3(4, 4), 256>>>(W2, out);
    attn_mma_kernel<<<dim3(NCH, BB), 256, SM_TOTAL>>>(enc_out, beta);
    ctx_reduce_kernel<<<BB, DD>>>();
    onew_gemm_kernel<<<dim3(4, 4), 256>>>(W3, out);
    logit_gemm_kernel<<<dim3(3, 4), 256>>>(W_out, out);
    softmax_logit_kernel<<<BB, 192>>>(out);
}

// round 7
// speedup vs baseline: 2.6365x; 1.0003x over previous
#include <cuda_runtime.h>
#include <cuda_bf16.h>
#include <math.h>
#include <cstdint>

#define BB   256   // batch
#define LL   1024  // enc length
#define DD   256   // ENC_D
#define HH   256   // DEC_H
#define EMBD 128
#define NOUT 172
#define KIN  640   // EMB + DEC_H(o_t) + DEC_H(h0)
#define NCH  8     // L / 128
#define NSM  148   // persistent grid

// ---------------- scratch (device globals; no allocation allowed) ----------
__device__ float g_A[BB * KIN];
__device__ float g_gates[BB * 4 * HH];
__device__ float g_hp[BB * DD];
__device__ float g_ctx[BB * DD];
__device__ float g_partS[BB * NCH];
__device__ float g_partC[BB * NCH * DD];
__device__ float g_logits[BB * NOUT];
__device__ uint32_t g_W1bf[256 * 132];   // W1 bf16, padded rows of 132 u32 (528 B) = 8448 uint4

// ---------------- helpers ---------------------------------------------------
__device__ __forceinline__ float tanh_fast(float x) {
    float y;
    asm("tanh.approx.f32 %0, %1;" : "=f"(y) : "f"(x));
    return y;
}
__device__ __forceinline__ float sigmoidf(float x) {
    return 1.0f / (1.0f + expf(-x));
}
__device__ __forceinline__ void mma_bf16(float* c, const uint32_t* a, const uint32_t* b) {
    asm volatile(
        "mma.sync.aligned.m16n8k16.row.col.f32.bf16.bf16.f32 "
        "{%0,%1,%2,%3}, {%4,%5,%6,%7}, {%8,%9}, {%0,%1,%2,%3};"
        : "+f"(c[0]), "+f"(c[1]), "+f"(c[2]), "+f"(c[3])
        : "r"(a[0]), "r"(a[1]), "r"(a[2]), "r"(a[3]), "r"(b[0]), "r"(b[1]));
}

// attn smem layout (bytes)
#define ROWB   528                    // 264 bf16 per padded row
#define SM_W1    0                    // 256 x 528 = 135168
#define SM_ENC   135168               // 128 x 528 = 67584
#define SM_HP    202752               // 256 f32
#define SM_BETA  203776               // 256 f32
#define SM_WS    204800               // 128 f32
#define SM_TOTAL 205312

#define W1_UINT4 8448                 // 135168 B / 16

// ---------------------------------------------------------------------------
// 1) Build LSTM input rows: A[b] = [emb[lasttarget[b]] | o_t[b] | h0[b]]
// ---------------------------------------------------------------------------
__global__ void prep_A_kernel(const float* __restrict__ emb,
                              const int* __restrict__ lt,
                              const float* __restrict__ o_t,
                              const float* __restrict__ h0) {
    int b = blockIdx.x;
    int k = threadIdx.x;
    float v;
    if (k < EMBD)       v = emb[lt[b] * EMBD + k];
    else if (k < 384)   v = o_t[b * HH + (k - EMBD)];
    else                v = h0[b * HH + (k - 384)];
    g_A[b * KIN + k] = v;
}

// ---------------------------------------------------------------------------
// 1b) Pre-pack W1 -> bf16, padded row-major [256][264]
// ---------------------------------------------------------------------------
__global__ void prep_W1_kernel(const float* __restrict__ W1) {
    int n = blockIdx.x;           // 256 rows
    int kp = threadIdx.x;         // 128 pairs
    __nv_bfloat162 h = __floats2bfloat162_rn(W1[n * DD + 2 * kp], W1[n * DD + 2 * kp + 1]);
    g_W1bf[n * 132 + kp] = *(uint32_t*)&h;
    if (kp < 4) g_W1bf[n * 132 + 128 + kp] = 0u;   // zero padding
}

// ---------------------------------------------------------------------------
// 2) gates = A @ [W_ih|W_hh]^T + b_ih + b_hh   (256 x 1024, K=640)
// ---------------------------------------------------------------------------
__global__ __launch_bounds__(256) void gates_gemm_kernel(
    const float* __restrict__ W_ih, const float* __restrict__ W_hh,
    const float* __restrict__ b_ih, const float* __restrict__ b_hh) {
    __shared__ float aT[32 * 65];
    __shared__ float bS[32 * 65];
    int n0 = blockIdx.x * 64;
    int m0 = blockIdx.y * 64;
    int tid = threadIdx.x;
    int tx = tid & 15, ty = tid >> 4;

    float acc[4][4];
#pragma unroll
    for (int i = 0; i < 4; i++)
#pragma unroll
        for (int j = 0; j < 4; j++) acc[i][j] = 0.f;

    for (int k0 = 0; k0 < KIN; k0 += 32) {
        __syncthreads();
#pragma unroll
        for (int rep = 0; rep < 8; rep++) {
            int idx = rep * 256 + tid;
            int r = idx >> 5, kk = idx & 31;
            aT[kk * 65 + r] = g_A[(m0 + r) * KIN + k0 + kk];
        }
#pragma unroll
        for (int rep = 0; rep < 8; rep++) {
            int idx = rep * 256 + tid;
            int j = idx >> 5, kk = idx & 31;
            int kg = k0 + kk;
            int jg = n0 + j;
            bS[kk * 65 + j] = (kg < 384) ? W_ih[jg * 384 + kg] : W_hh[jg * 256 + (kg - 384)];
        }
        __syncthreads();
#pragma unroll
        for (int kk = 0; kk < 32; kk++) {
            float a[4], w[4];
#pragma unroll
            for (int i = 0; i < 4; i++) a[i] = aT[kk * 65 + ty * 4 + i];
#pragma unroll
            for (int j = 0; j < 4; j++) w[j] = bS[kk * 65 + tx * 4 + j];
#pragma unroll
            for (int i = 0; i < 4; i++)
#pragma unroll
                for (int j = 0; j < 4; j++) acc[i][j] += a[i] * w[j];
        }
    }
#pragma unroll
    for (int i = 0; i < 4; i++) {
        int row = m0 + ty * 4 + i;
#pragma unroll
        for (int j = 0; j < 4; j++) {
            int col = n0 + tx * 4 + j;
            g_gates[row * 1024 + col] = acc[i][j] + b_ih[col] + b_hh[col];
        }
    }
}

// ---------------------------------------------------------------------------
// 3) LSTM cell -> h_t, c_t
// ---------------------------------------------------------------------------
__global__ void cell_kernel(const float* __restrict__ c0, float* __restrict__ out) {
    int b = blockIdx.x, d = threadIdx.x;
    const float* g = g_gates + b * 1024;
    float ig = g[d], fg = g[256 + d], gg = g[512 + d], og = g[768 + d];
    float c = sigmoidf(fg) * c0[b * HH + d] + sigmoidf(ig) * tanhf(gg);
    float h = sigmoidf(og) * tanhf(c);
    out[b * HH + d] = h;
    out[BB * HH + b * HH + d] = c;
}

// ---------------------------------------------------------------------------
// 4) hp = h_t @ W2^T  (256x256, K=256) — tiled GEMM
// ---------------------------------------------------------------------------
__global__ __launch_bounds__(256) void hproj_gemm_kernel(
    const float* __restrict__ W2, const float* __restrict__ out) {
    __shared__ float aT[32 * 65];
    __shared__ float bS[32 * 65];
    int n0 = blockIdx.x * 64;
    int m0 = blockIdx.y * 64;
    int tid = threadIdx.x;
    int tx = tid & 15, ty = tid >> 4;

    float acc[4][4];
#pragma unroll
    for (int i = 0; i < 4; i++)
#pragma unroll
        for (int j = 0; j < 4; j++) acc[i][j] = 0.f;

    for (int k0 = 0; k0 < HH; k0 += 32) {
        __syncthreads();
#pragma unroll
        for (int rep = 0; rep < 8; rep++) {
            int idx = rep * 256 + tid;
            int r = idx >> 5, kk = idx & 31;
            aT[kk * 65 + r] = out[(m0 + r) * HH + k0 + kk];
        }
#pragma unroll
        for (int rep = 0; rep < 8; rep++) {
            int idx = rep * 256 + tid;
            int j = idx >> 5, kk = idx & 31;
            bS[kk * 65 + j] = W2[(n0 + j) * HH + k0 + kk];
        }
        __syncthreads();
#pragma unroll
        for (int kk = 0; kk < 32; kk++) {
            float a[4], w[4];
#pragma unroll
            for (int i = 0; i < 4; i++) a[i] = aT[kk * 65 + ty * 4 + i];
#pragma unroll
            for (int j = 0; j < 4; j++) w[j] = bS[kk * 65 + tx * 4 + j];
#pragma unroll
            for (int i = 0; i < 4; i++)
#pragma unroll
                for (int j = 0; j < 4; j++) acc[i][j] += a[i] * w[j];
        }
    }
#pragma unroll
    for (int i = 0; i < 4; i++)
#pragma unroll
        for (int j = 0; j < 4; j++)
            g_hp[(m0 + ty * 4 + i) * DD + n0 + tx * 4 + j] = acc[i][j];
}

// ---------------------------------------------------------------------------
// 5) PERSISTENT attention (HMMA bf16), R3-validated inner tiling:
//    8 warps x 16 rows, nch-sequential over 4 x 64 cols, acc[8][4].
//    W1 resident in SMEM (FULL 8448-uint4 copy). A-fragments hoisted.
// ---------------------------------------------------------------------------
__global__ __launch_bounds__(256) void attn_mma_kernel(
    const float* __restrict__ enc, const float* __restrict__ beta) {
    extern __shared__ char sm[];
    float* hpS   = (float*)(sm + SM_HP);
    float* betaS = (float*)(sm + SM_BETA);
    float* wS    = (float*)(sm + SM_WS);
    char*  encS  = sm + SM_ENC;
    char*  w1S   = sm + SM_W1;

    int tid = threadIdx.x, wid = tid >> 5, lane = tid & 31;
    int g = lane >> 2, t = lane & 3;

    // W1 bf16 -> smem ONCE: FULL 8448 uint4 (135168 B)
    {
        const uint4* src = (const uint4*)g_W1bf;
        uint4* dst = (uint4*)w1S;
#pragma unroll 4
        for (int it = 0; it < 33; it++) dst[it * 256 + tid] = src[it * 256 + tid];
    }
    betaS[tid] = beta[tid];

    for (int tl = blockIdx.x; tl < BB * NCH; tl += NSM) {
        int b = tl >> 3, ch = tl & 7, l0 = ch << 7;
        hpS[tid] = g_hp[b * DD + tid];

        // enc tile fp32 -> bf16 padded smem rows (128 x 256, stride 528 B)
        const float* encB = enc + ((size_t)b * LL + l0) * DD;
#pragma unroll 4
        for (int it = 0; it < 32; it++) {
            int idx = it * 256 + tid;       // float4 index (8192 total)
            int r = idx >> 6;
            int c = (idx & 63) * 4;
            float4 v = *(const float4*)(encB + r * DD + c);
            __nv_bfloat162 p0 = __floats2bfloat162_rn(v.x, v.y);
            __nv_bfloat162 p1 = __floats2bfloat162_rn(v.z, v.w);
            uint2 u;
            u.x = *(uint32_t*)&p0;
            u.y = *(uint32_t*)&p1;
            *(uint2*)(encS + r * ROWB + c * 2) = u;
        }
        __syncthreads();

        int m0 = wid * 16;
        const char* arow = encS + (m0 + g) * ROWB + t * 4;

        // hoist A fragments once (reused across all 4 n-chunks)
        uint32_t a[16][4];
#pragma unroll
        for (int kb = 0; kb < 16; kb++) {
            const char* pa = arow + kb * 32;
            a[kb][0] = *(const uint32_t*)(pa);
            a[kb][1] = *(const uint32_t*)(pa + 8 * ROWB);
            a[kb][2] = *(const uint32_t*)(pa + 16);
            a[kb][3] = *(const uint32_t*)(pa + 8 * ROWB + 16);
        }

        float s0 = 0.f, s1 = 0.f;
#pragma unroll
        for (int nch = 0; nch < 4; nch++) {
            int n0 = nch * 64;
            float acc[8][4];
#pragma unroll
            for (int j = 0; j < 8; j++)
#pragma unroll
                for (int i = 0; i < 4; i++) acc[j][i] = 0.f;

#pragma unroll
            for (int kb = 0; kb < 16; kb++) {
#pragma unroll
                for (int jt = 0; jt < 8; jt++) {
                    const char* pb = w1S + (n0 + jt * 8 + g) * ROWB + t * 4 + kb * 32;
                    uint32_t bf[2];
                    bf[0] = *(const uint32_t*)(pb);
                    bf[1] = *(const uint32_t*)(pb + 16);
                    mma_bf16(acc[jt], a[kb], bf);
                }
            }
            // fused epilogue: s += beta_c * tanh(acc + hp_c)
#pragma unroll
            for (int jt = 0; jt < 8; jt++) {
                int c = n0 + jt * 8 + t * 2;
                float b0 = betaS[c], b1 = betaS[c + 1];
                float h0v = hpS[c], h1v = hpS[c + 1];
                s0 += b0 * tanh_fast(acc[jt][0] + h0v) + b1 * tanh_fast(acc[jt][1] + h1v);
                s1 += b0 * tanh_fast(acc[jt][2] + h0v) + b1 * tanh_fast(acc[jt][3] + h1v);
            }
        }
        // reduce across the quad (lanes sharing the same row)
        s0 += __shfl_xor_sync(0xffffffffu, s0, 1);
        s0 += __shfl_xor_sync(0xffffffffu, s0, 2);
        s1 += __shfl_xor_sync(0xffffffffu, s1, 1);
        s1 += __shfl_xor_sync(0xffffffffu, s1, 2);
        if (t == 0) {
            wS[m0 + g] = expf(s0);
            wS[m0 + g + 8] = expf(s1);
        }
        __syncthreads();

        if (tid < 32) {
            float ps = wS[tid] + wS[tid + 32] + wS[tid + 64] + wS[tid + 96];
#pragma unroll
            for (int o = 16; o > 0; o >>= 1) ps += __shfl_down_sync(0xffffffffu, ps, o);
            if (tid == 0) g_partS[b * NCH + ch] = ps;
        }

        // partial context in fp32 from gmem (tile is L2-hot)
        {
            float C = 0.f;
#pragma unroll 4
            for (int l = 0; l < 128; l++) C += wS[l] * encB[l * DD + tid];
            g_partC[(size_t)(b * NCH + ch) * DD + tid] = C;
        }
        __syncthreads();   // protect encS/hpS/wS before next tile
    }
}

// ---------------------------------------------------------------------------
// 6) context = sum(partC) / sum(partS)
// ---------------------------------------------------------------------------
__global__ void ctx_reduce_kernel() {
    int b = blockIdx.x, d = threadIdx.x;
    float S = 0.f, C = 0.f;
#pragma unroll
    for (int c = 0; c < NCH; c++) {
        S += g_partS[b * NCH + c];
        C += g_partC[(b * NCH + c) * DD + d];
    }
    g_ctx[b * DD + d] = C / S;
}

// ---------------------------------------------------------------------------
// 7) o_new = tanh([h_t | context] @ W3^T)  (256x256, K=512) — tiled
// ---------------------------------------------------------------------------
__global__ __launch_bounds__(256) void onew_gemm_kernel(
    const float* __restrict__ W3, float* __restrict__ out) {
    __shared__ float aT[32 * 65];
    __shared__ float bS[32 * 65];
    int n0 = blockIdx.x * 64;
    int m0 = blockIdx.y * 64;
    int tid = threadIdx.x;
    int tx = tid & 15, ty = tid >> 4;

    float acc[4][4];
#pragma unroll
    for (int i = 0; i < 4; i++)
#pragma unroll
        for (int j = 0; j < 4; j++) acc[i][j] = 0.f;

    for (int k0 = 0; k0 < 512; k0 += 32) {
        __syncthreads();
#pragma unroll
        for (int rep = 0; rep < 8; rep++) {
            int idx = rep * 256 + tid;
            int r = idx >> 5, kk = idx & 31;
            int kg = k0 + kk;
            aT[kk * 65 + r] = (kg < 256) ? out[(m0 + r) * HH + kg]
                                         : g_ctx[(m0 + r) * DD + (kg - 256)];
        }
#pragma unroll
        for (int rep = 0; rep < 8; rep++) {
            int idx = rep * 256 + tid;
            int j = idx >> 5, kk = idx & 31;
            bS[kk * 65 + j] = W3[(n0 + j) * 512 + k0 + kk];
        }
        __syncthreads();
#pragma unroll
        for (int kk = 0; kk < 32; kk++) {
            float a[4], w[4];
#pragma unroll
            for (int i = 0; i < 4; i++) a[i] = aT[kk * 65 + ty * 4 + i];
#pragma unroll
            for (int j = 0; j < 4; j++) w[j] = bS[kk * 65 + tx * 4 + j];
#pragma unroll
            for (int i = 0; i < 4; i++)
#pragma unroll
                for (int j = 0; j < 4; j++) acc[i][j] += a[i] * w[j];
        }
    }
#pragma unroll
    for (int i = 0; i < 4; i++)
#pragma unroll
        for (int j = 0; j < 4; j++)
            out[2 * BB * HH + (m0 + ty * 4 + i) * HH + n0 + tx * 4 + j] = tanhf(acc[i][j]);
}

// ---------------------------------------------------------------------------
// 8) raw logits = o_new @ W_out^T  (256x172, K=256) — tiled
// ---------------------------------------------------------------------------
__global__ __launch_bounds__(256) void logit_gemm_kernel(
    const float* __restrict__ Wout, const float* __restrict__ out) {
    __shared__ float aT[32 * 65];
    __shared__ float bS[32 * 65];
    int n0 = blockIdx.x * 64;
    int m0 = blockIdx.y * 64;
    int tid = threadIdx.x;
    int tx = tid & 15, ty = tid >> 4;
    const float* onew = out + 2 * BB * HH;

    float acc[4][4];
#pragma unroll
    for (int i = 0; i < 4; i++)
#pragma unroll
        for (int j = 0; j < 4; j++) acc[i][j] = 0.f;

    for (int k0 = 0; k0 < HH; k0 += 32) {
        __syncthreads();
#pragma unroll
        for (int rep = 0; rep < 8; rep++) {
            int idx = rep * 256 + tid;
            int r = idx >> 5, kk = idx & 31;
            aT[kk * 65 + r] = onew[(m0 + r) * HH + k0 + kk];
        }
#pragma unroll
        for (int rep = 0; rep < 8; rep++) {
            int idx = rep * 256 + tid;
            int j = idx >> 5, kk = idx & 31;
            int jg = n0 + j;
            bS[kk * 65 + j] = (jg < NOUT) ? Wout[jg * HH + k0 + kk] : 0.f;
        }
        __syncthreads();
#pragma unroll
        for (int kk = 0; kk < 32; kk++) {
            float a[4], w[4];
#pragma unroll
            for (int i = 0; i < 4; i++) a[i] = aT[kk * 65 + ty * 4 + i];
#pragma unroll
            for (int j = 0; j < 4; j++) w[j] = bS[kk * 65 + tx * 4 + j];
#pragma unroll
            for (int i = 0; i < 4; i++)
#pragma unroll
                for (int j = 0; j < 4; j++) acc[i][j] += a[i] * w[j];
        }
    }
#pragma unroll
    for (int i = 0; i < 4; i++) {
        int row = m0 + ty * 4 + i;
#pragma unroll
        for (int j = 0; j < 4; j++) {
            int col = n0 + tx * 4 + j;
            if (col < NOUT) g_logits[row * NOUT + col] = acc[i][j];
        }
    }
}

// ---------------------------------------------------------------------------
// 9) logit softmax
// ---------------------------------------------------------------------------
__global__ void softmax_logit_kernel(float* __restrict__ out) {
    __shared__ float lg[NOUT];
    __shared__ float red;
    int b = blockIdx.x, t = threadIdx.x;
    if (t < NOUT) lg[t] = g_logits[b * NOUT + t];
    __syncthreads();
    if (t == 0) {
        float m = lg[0];
        for (int i = 1; i < NOUT; i++) m = fmaxf(m, lg[i]);
        red = m;
    }
    __syncthreads();
    float e = (t < NOUT) ? expf(lg[t] - red) : 0.f;
    __syncthreads();
    if (t < NOUT) lg[t] = e;
    __syncthreads();
    if (t == 0) {
        float s = 0.f;
        for (int i = 0; i < NOUT; i++) s += lg[i];
        red = s;
    }
    __syncthreads();
    if (t < NOUT) out[3 * BB * HH + b * NOUT + t] = lg[t] / red;
}

// ---------------------------------------------------------------------------
extern "C" void kernel_launch(void* const* d_in, const int* in_sizes, int n_in,
                              void* d_out, int out_size) {
    const float* h0      = (const float*)d_in[0];
    const float* c0      = (const float*)d_in[1];
    const float* o_t     = (const float*)d_in[2];
    const float* enc_out = (const float*)d_in[3];
    const int*   lt      = (const int*)  d_in[4];
    const float* emb     = (const float*)d_in[5];
    const float* W_ih    = (const float*)d_in[6];
    const float* W_hh    = (const float*)d_in[7];
    const float* b_ih    = (const float*)d_in[8];
    const float* b_hh    = (const float*)d_in[9];
    const float* W1      = (const float*)d_in[10];
    const float* W2      = (const float*)d_in[11];
    const float* W3      = (const float*)d_in[12];
    const float* W_out   = (const float*)d_in[13];
    const float* beta    = (const float*)d_in[14];
    float* out = (float*)d_out;

    cudaFuncSetAttribute(attn_mma_kernel, cudaFuncAttributeMaxDynamicSharedMemorySize, SM_TOTAL);

    prep_A_kernel<<<BB, KIN>>>(emb, lt, o_t, h0);
    prep_W1_kernel<<<256, 128>>>(W1);
    gates_gemm_kernel<<<dim3(16, 4), 256>>>(W_ih, W_hh, b_ih, b_hh);
    cell_kernel<<<BB, HH>>>(c0, out);
    hproj_gemm_kernel<<<dim3(4, 4), 256>>>(W2, out);
    attn_mma_kernel<<<NSM, 256, SM_TOTAL>>>(enc_out, beta);
    ctx_reduce_kernel<<<BB, DD>>>();
    onew_gemm_kernel<<<dim3(4, 4), 256>>>(W3, out);
    logit_gemm_kernel<<<dim3(3, 4), 256>>>(W_out, out);
    softmax_logit_kernel<<<BB, 192>>>(out);
}

// round 8
// speedup vs baseline: 3.1532x; 1.1960x over previous
#include <cuda_runtime.h>
#include <cuda_bf16.h>
#include <math.h>
#include <cstdint>

#define BB   256   // batch
#define LL   1024  // enc length
#define DD   256   // ENC_D
#define HH   256   // DEC_H
#define EMBD 128
#define NOUT 172
#define KIN  640   // EMB + DEC_H(o_t) + DEC_H(h0)
#define NCH  8     // L / 128
#define NSM  148   // persistent grid

// ---------------- scratch (device globals; no allocation allowed) ----------
__device__ float g_A[BB * KIN];
__device__ float g_gates[BB * 4 * HH];
__device__ float g_hp[BB * DD];
__device__ float g_ctx[BB * DD];
__device__ float g_partS[BB * NCH];
__device__ float g_partC[BB * NCH * DD];
__device__ float g_logits[BB * NOUT];
__device__ uint32_t g_W1bf[256 * 132];   // W1 bf16, K-PERMUTED padded rows (528 B)

// ---------------- helpers ---------------------------------------------------
__device__ __forceinline__ float tanh_fast(float x) {
    float y;
    asm("tanh.approx.f32 %0, %1;" : "=f"(y) : "f"(x));
    return y;
}
__device__ __forceinline__ float sigmoidf(float x) {
    return 1.0f / (1.0f + expf(-x));
}
__device__ __forceinline__ void mma_bf16(float* c, const uint32_t* a, uint32_t b0, uint32_t b1) {
    asm volatile(
        "mma.sync.aligned.m16n8k16.row.col.f32.bf16.bf16.f32 "
        "{%0,%1,%2,%3}, {%4,%5,%6,%7}, {%8,%9}, {%0,%1,%2,%3};"
        : "+f"(c[0]), "+f"(c[1]), "+f"(c[2]), "+f"(c[3])
        : "r"(a[0]), "r"(a[1]), "r"(a[2]), "r"(a[3]), "r"(b0), "r"(b1));
}

// attn smem layout (bytes)
#define ROWB   528                    // 264 bf16 per padded row
#define SM_W1    0                    // 256 x 528 = 135168
#define SM_ENC   135168               // 128 x 528 = 67584
#define SM_HP    202752               // 256 f32
#define SM_BETA  203776               // 256 f32
#define SM_WS    204800               // 128 f32 (512 B)
#define SM_CTX   205312               // 256 f32 (1024 B)
#define SM_TOTAL 206336

// ---------------------------------------------------------------------------
// 1) Build LSTM input rows: A[b] = [emb[lasttarget[b]] | o_t[b] | h0[b]]
// ---------------------------------------------------------------------------
__global__ void prep_A_kernel(const float* __restrict__ emb,
                              const int* __restrict__ lt,
                              const float* __restrict__ o_t,
                              const float* __restrict__ h0) {
    int b = blockIdx.x;
    int k = threadIdx.x;
    float v;
    if (k < EMBD)       v = emb[lt[b] * EMBD + k];
    else if (k < 384)   v = o_t[b * HH + (k - EMBD)];
    else                v = h0[b * HH + (k - 384)];
    g_A[b * KIN + k] = v;
}

// ---------------------------------------------------------------------------
// 1b) Pre-pack W1 -> bf16, padded rows, K-PERMUTED so that the two B-fragment
//     regs of one HMMA are adjacent (single LDS.64):
//     pair at even k -> u32 pos (k>>4)*8 + ((k&7)>>1)*2 + ((k>>3)&1)
// ---------------------------------------------------------------------------
__global__ void prep_W1_kernel(const float* __restrict__ W1) {
    int n = blockIdx.x;           // 256 rows
    int kp = threadIdx.x;         // 128 pairs
    int k = 2 * kp;
    __nv_bfloat162 h = __floats2bfloat162_rn(W1[n * DD + k], W1[n * DD + k + 1]);
    int pos = ((k >> 4) << 3) + (((k & 7) >> 1) << 1) + ((k >> 3) & 1);
    g_W1bf[n * 132 + pos] = *(uint32_t*)&h;
    if (kp < 4) g_W1bf[n * 132 + 128 + kp] = 0u;   // zero padding
}

// ---------------------------------------------------------------------------
// 2) gates = A @ [W_ih|W_hh]^T + b_ih + b_hh   (256 x 1024, K=640)
// ---------------------------------------------------------------------------
__global__ __launch_bounds__(256) void gates_gemm_kernel(
    const float* __restrict__ W_ih, const float* __restrict__ W_hh,
    const float* __restrict__ b_ih, const float* __restrict__ b_hh) {
    __shared__ float aT[32 * 65];
    __shared__ float bS[32 * 65];
    int n0 = blockIdx.x * 64;
    int m0 = blockIdx.y * 64;
    int tid = threadIdx.x;
    int tx = tid & 15, ty = tid >> 4;

    float acc[4][4];
#pragma unroll
    for (int i = 0; i < 4; i++)
#pragma unroll
        for (int j = 0; j < 4; j++) acc[i][j] = 0.f;

    for (int k0 = 0; k0 < KIN; k0 += 32) {
        __syncthreads();
#pragma unroll
        for (int rep = 0; rep < 8; rep++) {
            int idx = rep * 256 + tid;
            int r = idx >> 5, kk = idx & 31;
            aT[kk * 65 + r] = g_A[(m0 + r) * KIN + k0 + kk];
        }
#pragma unroll
        for (int rep = 0; rep < 8; rep++) {
            int idx = rep * 256 + tid;
            int j = idx >> 5, kk = idx & 31;
            int kg = k0 + kk;
            int jg = n0 + j;
            bS[kk * 65 + j] = (kg < 384) ? W_ih[jg * 384 + kg] : W_hh[jg * 256 + (kg - 384)];
        }
        __syncthreads();
#pragma unroll
        for (int kk = 0; kk < 32; kk++) {
            float a[4], w[4];
#pragma unroll
            for (int i = 0; i < 4; i++) a[i] = aT[kk * 65 + ty * 4 + i];
#pragma unroll
            for (int j = 0; j < 4; j++) w[j] = bS[kk * 65 + tx * 4 + j];
#pragma unroll
            for (int i = 0; i < 4; i++)
#pragma unroll
                for (int j = 0; j < 4; j++) acc[i][j] += a[i] * w[j];
        }
    }
#pragma unroll
    for (int i = 0; i < 4; i++) {
        int row = m0 + ty * 4 + i;
#pragma unroll
        for (int j = 0; j < 4; j++) {
            int col = n0 + tx * 4 + j;
            g_gates[row * 1024 + col] = acc[i][j] + b_ih[col] + b_hh[col];
        }
    }
}

// ---------------------------------------------------------------------------
// 3) LSTM cell -> h_t, c_t
// ---------------------------------------------------------------------------
__global__ void cell_kernel(const float* __restrict__ c0, float* __restrict__ out) {
    int b = blockIdx.x, d = threadIdx.x;
    const float* g = g_gates + b * 1024;
    float ig = g[d], fg = g[256 + d], gg = g[512 + d], og = g[768 + d];
    float c = sigmoidf(fg) * c0[b * HH + d] + sigmoidf(ig) * tanhf(gg);
    float h = sigmoidf(og) * tanhf(c);
    out[b * HH + d] = h;
    out[BB * HH + b * HH + d] = c;
}

// ---------------------------------------------------------------------------
// 4) hp = h_t @ W2^T  (256x256, K=256) — tiled GEMM
// ---------------------------------------------------------------------------
__global__ __launch_bounds__(256) void hproj_gemm_kernel(
    const float* __restrict__ W2, const float* __restrict__ out) {
    __shared__ float aT[32 * 65];
    __shared__ float bS[32 * 65];
    int n0 = blockIdx.x * 64;
    int m0 = blockIdx.y * 64;
    int tid = threadIdx.x;
    int tx = tid & 15, ty = tid >> 4;

    float acc[4][4];
#pragma unroll
    for (int i = 0; i < 4; i++)
#pragma unroll
        for (int j = 0; j < 4; j++) acc[i][j] = 0.f;

    for (int k0 = 0; k0 < HH; k0 += 32) {
        __syncthreads();
#pragma unroll
        for (int rep = 0; rep < 8; rep++) {
            int idx = rep * 256 + tid;
            int r = idx >> 5, kk = idx & 31;
            aT[kk * 65 + r] = out[(m0 + r) * HH + k0 + kk];
        }
#pragma unroll
        for (int rep = 0; rep < 8; rep++) {
            int idx = rep * 256 + tid;
            int j = idx >> 5, kk = idx & 31;
            bS[kk * 65 + j] = W2[(n0 + j) * HH + k0 + kk];
        }
        __syncthreads();
#pragma unroll
        for (int kk = 0; kk < 32; kk++) {
            float a[4], w[4];
#pragma unroll
            for (int i = 0; i < 4; i++) a[i] = aT[kk * 65 + ty * 4 + i];
#pragma unroll
            for (int j = 0; j < 4; j++) w[j] = bS[kk * 65 + tx * 4 + j];
#pragma unroll
            for (int i = 0; i < 4; i++)
#pragma unroll
                for (int j = 0; j < 4; j++) acc[i][j] += a[i] * w[j];
        }
    }
#pragma unroll
    for (int i = 0; i < 4; i++)
#pragma unroll
        for (int j = 0; j < 4; j++)
            g_hp[(m0 + ty * 4 + i) * DD + n0 + tx * 4 + j] = acc[i][j];
}

// ---------------------------------------------------------------------------
// 5) PERSISTENT attention (HMMA bf16):
//    - per-warp enc staging (own 16 rows) -> no block barrier before MMA
//    - B fragments via single LDS.64 from K-permuted W1
//    - split context pass (2 groups x 64 rows) in fp32
// ---------------------------------------------------------------------------
__global__ __launch_bounds__(256) void attn_mma_kernel(
    const float* __restrict__ enc, const float* __restrict__ beta) {
    extern __shared__ char sm[];
    float* hpS   = (float*)(sm + SM_HP);
    float* betaS = (float*)(sm + SM_BETA);
    float* wS    = (float*)(sm + SM_WS);
    float* ctxS  = (float*)(sm + SM_CTX);
    char*  encS  = sm + SM_ENC;
    char*  w1S   = sm + SM_W1;

    int tid = threadIdx.x, wid = tid >> 5, lane = tid & 31;
    int g = lane >> 2, t = lane & 3;
    int m0 = wid * 16;

    // W1 bf16 (K-permuted) -> smem ONCE: FULL 8448 uint4 (135168 B)
    {
        const uint4* src = (const uint4*)g_W1bf;
        uint4* dst = (uint4*)w1S;
#pragma unroll 4
        for (int it = 0; it < 33; it++) dst[it * 256 + tid] = src[it * 256 + tid];
    }
    betaS[tid] = beta[tid];
    __syncthreads();

    for (int tl = blockIdx.x; tl < BB * NCH; tl += NSM) {
        int b = tl >> 3, ch = tl & 7, l0 = ch << 7;
        const float* encB = enc + ((size_t)b * LL + l0) * DD;

        // hp: each warp loads the full 256 values it needs (identical writes ok)
#pragma unroll
        for (int i = 0; i < 8; i++) hpS[i * 32 + lane] = g_hp[b * DD + i * 32 + lane];

        // per-warp enc staging: rows [m0, m0+16) fp32 -> bf16 padded smem
        {
            const float* wrow = encB + m0 * DD;
            char* sdst = encS + m0 * ROWB;
#pragma unroll 8
            for (int it = 0; it < 32; it++) {
                int idx = it * 32 + lane;       // 1024 float4 per warp
                int rl = idx >> 6;
                int c4 = idx & 63;
                float4 v = *(const float4*)(wrow + rl * DD + c4 * 4);
                __nv_bfloat162 p0 = __floats2bfloat162_rn(v.x, v.y);
                __nv_bfloat162 p1 = __floats2bfloat162_rn(v.z, v.w);
                uint2 u;
                u.x = *(uint32_t*)&p0;
                u.y = *(uint32_t*)&p1;
                *(uint2*)(sdst + rl * ROWB + c4 * 8) = u;
            }
        }
        __syncwarp();

        // hoist A fragments (own rows only)
        const char* arow = encS + (m0 + g) * ROWB + t * 4;
        uint32_t a[16][4];
#pragma unroll
        for (int kb = 0; kb < 16; kb++) {
            const char* pa = arow + kb * 32;
            a[kb][0] = *(const uint32_t*)(pa);
            a[kb][1] = *(const uint32_t*)(pa + 8 * ROWB);
            a[kb][2] = *(const uint32_t*)(pa + 16);
            a[kb][3] = *(const uint32_t*)(pa + 8 * ROWB + 16);
        }

        float s0 = 0.f, s1 = 0.f;
#pragma unroll
        for (int nch = 0; nch < 4; nch++) {
            int n0 = nch * 64;
            float acc[8][4];
#pragma unroll
            for (int j = 0; j < 8; j++)
#pragma unroll
                for (int i = 0; i < 4; i++) acc[j][i] = 0.f;

#pragma unroll
            for (int kb = 0; kb < 16; kb++) {
#pragma unroll
                for (int jt = 0; jt < 8; jt++) {
                    uint2 bf = *(const uint2*)(w1S + (n0 + jt * 8 + g) * ROWB + kb * 32 + t * 8);
                    mma_bf16(acc[jt], a[kb], bf.x, bf.y);
                }
            }
            // fused epilogue: s += beta_c * tanh(acc + hp_c)
#pragma unroll
            for (int jt = 0; jt < 8; jt++) {
                int c = n0 + jt * 8 + t * 2;
                float b0 = betaS[c], b1 = betaS[c + 1];
                float h0v = hpS[c], h1v = hpS[c + 1];
                s0 += b0 * tanh_fast(acc[jt][0] + h0v) + b1 * tanh_fast(acc[jt][1] + h1v);
                s1 += b0 * tanh_fast(acc[jt][2] + h0v) + b1 * tanh_fast(acc[jt][3] + h1v);
            }
        }
        // reduce across the quad (lanes sharing the same row)
        s0 += __shfl_xor_sync(0xffffffffu, s0, 1);
        s0 += __shfl_xor_sync(0xffffffffu, s0, 2);
        s1 += __shfl_xor_sync(0xffffffffu, s1, 1);
        s1 += __shfl_xor_sync(0xffffffffu, s1, 2);
        if (t == 0) {
            wS[m0 + g] = expf(s0);
            wS[m0 + g + 8] = expf(s1);
        }
        __syncthreads();   // S1: wS complete

        if (tid < 32) {
            float ps = wS[tid] + wS[tid + 32] + wS[tid + 64] + wS[tid + 96];
#pragma unroll
            for (int o = 16; o > 0; o >>= 1) ps += __shfl_down_sync(0xffffffffu, ps, o);
            if (tid == 0) g_partS[b * NCH + ch] = ps;
        }

        // split context pass: group (half) handles 64 rows, fp32, float2 cols
        {
            int p = tid & 127, half = tid >> 7;
            float C0 = 0.f, C1 = 0.f;
            const float* base = encB + (half * 64) * DD + 2 * p;
            const float* wHalf = wS + half * 64;
#pragma unroll 8
            for (int r = 0; r < 64; r++) {
                float2 v = *(const float2*)(base + r * DD);
                float w = wHalf[r];
                C0 += w * v.x;
                C1 += w * v.y;
            }
            if (half) {
                ctxS[2 * p] = C0;
                ctxS[2 * p + 1] = C1;
            }
            __syncthreads();   // S2a: ctxS half-1 complete
            if (!half) {
                float* dst = g_partC + (size_t)(b * NCH + ch) * DD;
                dst[2 * p] = C0 + ctxS[2 * p];
                dst[2 * p + 1] = C1 + ctxS[2 * p + 1];
            }
        }
        __syncthreads();   // S2: protect wS/hpS/ctxS before next tile
    }
}

// ---------------------------------------------------------------------------
// 6) context = sum(partC) / sum(partS)
// ---------------------------------------------------------------------------
__global__ void ctx_reduce_kernel() {
    int b = blockIdx.x, d = threadIdx.x;
    float S = 0.f, C = 0.f;
#pragma unroll
    for (int c = 0; c < NCH; c++) {
        S += g_partS[b * NCH + c];
        C += g_partC[(b * NCH + c) * DD + d];
    }
    g_ctx[b * DD + d] = C / S;
}

// ---------------------------------------------------------------------------
// 7) o_new = tanh([h_t | context] @ W3^T)  (256x256, K=512) — tiled
// ---------------------------------------------------------------------------
__global__ __launch_bounds__(256) void onew_gemm_kernel(
    const float* __restrict__ W3, float* __restrict__ out) {
    __shared__ float aT[32 * 65];
    __shared__ float bS[32 * 65];
    int n0 = blockIdx.x * 64;
    int m0 = blockIdx.y * 64;
    int tid = threadIdx.x;
    int tx = tid & 15, ty = tid >> 4;

    float acc[4][4];
#pragma unroll
    for (int i = 0; i < 4; i++)
#pragma unroll
        for (int j = 0; j < 4; j++) acc[i][j] = 0.f;

    for (int k0 = 0; k0 < 512; k0 += 32) {
        __syncthreads();
#pragma unroll
        for (int rep = 0; rep < 8; rep++) {
            int idx = rep * 256 + tid;
            int r = idx >> 5, kk = idx & 31;
            int kg = k0 + kk;
            aT[kk * 65 + r] = (kg < 256) ? out[(m0 + r) * HH + kg]
                                         : g_ctx[(m0 + r) * DD + (kg - 256)];
        }
#pragma unroll
        for (int rep = 0; rep < 8; rep++) {
            int idx = rep * 256 + tid;
            int j = idx >> 5, kk = idx & 31;
            bS[kk * 65 + j] = W3[(n0 + j) * 512 + k0 + kk];
        }
        __syncthreads();
#pragma unroll
        for (int kk = 0; kk < 32; kk++) {
            float a[4], w[4];
#pragma unroll
            for (int i = 0; i < 4; i++) a[i] = aT[kk * 65 + ty * 4 + i];
#pragma unroll
            for (int j = 0; j < 4; j++) w[j] = bS[kk * 65 + tx * 4 + j];
#pragma unroll
            for (int i = 0; i < 4; i++)
#pragma unroll
                for (int j = 0; j < 4; j++) acc[i][j] += a[i] * w[j];
        }
    }
#pragma unroll
    for (int i = 0; i < 4; i++)
#pragma unroll
        for (int j = 0; j < 4; j++)
            out[2 * BB * HH + (m0 + ty * 4 + i) * HH + n0 + tx * 4 + j] = tanhf(acc[i][j]);
}

// ---------------------------------------------------------------------------
// 8) raw logits = o_new @ W_out^T  (256x172, K=256) — tiled
// ---------------------------------------------------------------------------
__global__ __launch_bounds__(256) void logit_gemm_kernel(
    const float* __restrict__ Wout, const float* __restrict__ out) {
    __shared__ float aT[32 * 65];
    __shared__ float bS[32 * 65];
    int n0 = blockIdx.x * 64;
    int m0 = blockIdx.y * 64;
    int tid = threadIdx.x;
    int tx = tid & 15, ty = tid >> 4;
    const float* onew = out + 2 * BB * HH;

    float acc[4][4];
#pragma unroll
    for (int i = 0; i < 4; i++)
#pragma unroll
        for (int j = 0; j < 4; j++) acc[i][j] = 0.f;

    for (int k0 = 0; k0 < HH; k0 += 32) {
        __syncthreads();
#pragma unroll
        for (int rep = 0; rep < 8; rep++) {
            int idx = rep * 256 + tid;
            int r = idx >> 5, kk = idx & 31;
            aT[kk * 65 + r] = onew[(m0 + r) * HH + k0 + kk];
        }
#pragma unroll
        for (int rep = 0; rep < 8; rep++) {
            int idx = rep * 256 + tid;
            int j = idx >> 5, kk = idx & 31;
            int jg = n0 + j;
            bS[kk * 65 + j] = (jg < NOUT) ? Wout[jg * HH + k0 + kk] : 0.f;
        }
        __syncthreads();
#pragma unroll
        for (int kk = 0; kk < 32; kk++) {
            float a[4], w[4];
#pragma unroll
            for (int i = 0; i < 4; i++) a[i] = aT[kk * 65 + ty * 4 + i];
#pragma unroll
            for (int j = 0; j < 4; j++) w[j] = bS[kk * 65 + tx * 4 + j];
#pragma unroll
            for (int i = 0; i < 4; i++)
#pragma unroll
                for (int j = 0; j < 4; j++) acc[i][j] += a[i] * w[j];
        }
    }
#pragma unroll
    for (int i = 0; i < 4; i++) {
        int row = m0 + ty * 4 + i;
#pragma unroll
        for (int j = 0; j < 4; j++) {
            int col = n0 + tx * 4 + j;
            if (col < NOUT) g_logits[row * NOUT + col] = acc[i][j];
        }
    }
}

// ---------------------------------------------------------------------------
// 9) logit softmax
// ---------------------------------------------------------------------------
__global__ void softmax_logit_kernel(float* __restrict__ out) {
    __shared__ float lg[NOUT];
    __shared__ float red;
    int b = blockIdx.x, t = threadIdx.x;
    if (t < NOUT) lg[t] = g_logits[b * NOUT + t];
    __syncthreads();
    if (t == 0) {
        float m = lg[0];
        for (int i = 1; i < NOUT; i++) m = fmaxf(m, lg[i]);
        red = m;
    }
    __syncthreads();
    float e = (t < NOUT) ? expf(lg[t] - red) : 0.f;
    __syncthreads();
    if (t < NOUT) lg[t] = e;
    __syncthreads();
    if (t == 0) {
        float s = 0.f;
        for (int i = 0; i < NOUT; i++) s += lg[i];
        red = s;
    }
    __syncthreads();
    if (t < NOUT) out[3 * BB * HH + b * NOUT + t] = lg[t] / red;
}

// ---------------------------------------------------------------------------
extern "C" void kernel_launch(void* const* d_in, const int* in_sizes, int n_in,
                              void* d_out, int out_size) {
    const float* h0      = (const float*)d_in[0];
    const float* c0      = (const float*)d_in[1];
    const float* o_t     = (const float*)d_in[2];
    const float* enc_out = (const float*)d_in[3];
    const int*   lt      = (const int*)  d_in[4];
    const float* emb     = (const float*)d_in[5];
    const float* W_ih    = (const float*)d_in[6];
    const float* W_hh    = (const float*)d_in[7];
    const float* b_ih    = (const float*)d_in[8];
    const float* b_hh    = (const float*)d_in[9];
    const float* W1      = (const float*)d_in[10];
    const float* W2      = (const float*)d_in[11];
    const float* W3      = (const float*)d_in[12];
    const float* W_out   = (const float*)d_in[13];
    const float* beta    = (const float*)d_in[14];
    float* out = (float*)d_out;

    cudaFuncSetAttribute(attn_mma_kernel, cudaFuncAttributeMaxDynamicSharedMemorySize, SM_TOTAL);

    prep_A_kernel<<<BB, KIN>>>(emb, lt, o_t, h0);
    prep_W1_kernel<<<256, 128>>>(W1);
    gates_gemm_kernel<<<dim3(16, 4), 256>>>(W_ih, W_hh, b_ih, b_hh);
    cell_kernel<<<BB, HH>>>(c0, out);
    hproj_gemm_kernel<<<dim3(4, 4), 256>>>(W2, out);
    attn_mma_kernel<<<NSM, 256, SM_TOTAL>>>(enc_out, beta);
    ctx_reduce_kernel<<<BB, DD>>>();
    onew_gemm_kernel<<<dim3(4, 4), 256>>>(W3, out);
    logit_gemm_kernel<<<dim3(3, 4), 256>>>(W_out, out);
    softmax_logit_kernel<<<BB, 192>>>(out);
}

// round 9
// speedup vs baseline: 3.4567x; 1.0962x over previous
#include <cuda_runtime.h>
#include <cuda_bf16.h>
#include <math.h>
#include <cstdint>

#define BB   256   // batch
#define LL   1024  // enc length
#define DD   256   // ENC_D
#define HH   256   // DEC_H
#define EMBD 128
#define NOUT 172
#define KIN  640   // EMB + DEC_H(o_t) + DEC_H(h0)
#define NCH  8     // L / 128
#define NSM  148   // persistent grid

// ---------------- scratch (device globals; no allocation allowed) ----------
__device__ float g_A[BB * KIN];
__device__ float g_gates[BB * 4 * HH];
__device__ float g_hp[BB * DD];
__device__ float g_ctx[BB * DD];
__device__ float g_partS[BB * NCH];
__device__ float g_partC[BB * NCH * DD];
__device__ float g_logits[BB * NOUT];
__device__ uint32_t g_W1bf[256 * 132];   // W1 bf16, K-PERMUTED padded rows (528 B)

// ---------------- helpers ---------------------------------------------------
__device__ __forceinline__ float tanh_fast(float x) {
    float y;
    asm("tanh.approx.f32 %0, %1;" : "=f"(y) : "f"(x));
    return y;
}
__device__ __forceinline__ float sigmoidf(float x) {
    return 1.0f / (1.0f + expf(-x));
}
__device__ __forceinline__ void mma_bf16(float* c,
                                         uint32_t a0, uint32_t a1, uint32_t a2, uint32_t a3,
                                         uint32_t b0, uint32_t b1) {
    asm volatile(
        "mma.sync.aligned.m16n8k16.row.col.f32.bf16.bf16.f32 "
        "{%0,%1,%2,%3}, {%4,%5,%6,%7}, {%8,%9}, {%0,%1,%2,%3};"
        : "+f"(c[0]), "+f"(c[1]), "+f"(c[2]), "+f"(c[3])
        : "r"(a0), "r"(a1), "r"(a2), "r"(a3), "r"(b0), "r"(b1));
}

// attn smem layout (bytes)
#define ROWB   528                    // 264 bf16 per padded row
#define SM_W1    0                    // 256 x 528 = 135168
#define SM_ENC   135168               // 128 x 528 = 67584
#define SM_HP    202752               // 256 f32
#define SM_BETA  203776               // 256 f32
#define SM_WS    204800               // 128 f32 (512 B)
#define SM_CTX   205312               // 256 f32 (1024 B)
#define SM_SRED  206336               // 128 x 5 f32 = 2560 B
#define SM_TOTAL 208896

// K-pair permutation (u32 position within a row) shared by W1 pack + enc staging:
// even k -> pos = (k>>4)*8 + ((k&7)>>1)*2 + ((k>>3)&1)
__device__ __forceinline__ int kperm(int k) {
    return ((k >> 4) << 3) + (((k & 7) >> 1) << 1) + ((k >> 3) & 1);
}

// ---------------------------------------------------------------------------
// 1) Build LSTM input rows: A[b] = [emb[lasttarget[b]] | o_t[b] | h0[b]]
// ---------------------------------------------------------------------------
__global__ void prep_A_kernel(const float* __restrict__ emb,
                              const int* __restrict__ lt,
                              const float* __restrict__ o_t,
                              const float* __restrict__ h0) {
    int b = blockIdx.x;
    int k = threadIdx.x;
    float v;
    if (k < EMBD)       v = emb[lt[b] * EMBD + k];
    else if (k < 384)   v = o_t[b * HH + (k - EMBD)];
    else                v = h0[b * HH + (k - 384)];
    g_A[b * KIN + k] = v;
}

// ---------------------------------------------------------------------------
// 1b) Pre-pack W1 -> bf16, padded rows, K-permuted (LDS.64 B fragments)
// ---------------------------------------------------------------------------
__global__ void prep_W1_kernel(const float* __restrict__ W1) {
    int n = blockIdx.x;           // 256 rows
    int kp = threadIdx.x;         // 128 pairs
    int k = 2 * kp;
    __nv_bfloat162 h = __floats2bfloat162_rn(W1[n * DD + k], W1[n * DD + k + 1]);
    g_W1bf[n * 132 + kperm(k)] = *(uint32_t*)&h;
    if (kp < 4) g_W1bf[n * 132 + 128 + kp] = 0u;   // zero padding
}

// ---------------------------------------------------------------------------
// 2) gates = A @ [W_ih|W_hh]^T + b_ih + b_hh   (256 x 1024, K=640)
// ---------------------------------------------------------------------------
__global__ __launch_bounds__(256) void gates_gemm_kernel(
    const float* __restrict__ W_ih, const float* __restrict__ W_hh,
    const float* __restrict__ b_ih, const float* __restrict__ b_hh) {
    __shared__ float aT[32 * 65];
    __shared__ float bS[32 * 65];
    int n0 = blockIdx.x * 64;
    int m0 = blockIdx.y * 64;
    int tid = threadIdx.x;
    int tx = tid & 15, ty = tid >> 4;

    float acc[4][4];
#pragma unroll
    for (int i = 0; i < 4; i++)
#pragma unroll
        for (int j = 0; j < 4; j++) acc[i][j] = 0.f;

    for (int k0 = 0; k0 < KIN; k0 += 32) {
        __syncthreads();
#pragma unroll
        for (int rep = 0; rep < 8; rep++) {
            int idx = rep * 256 + tid;
            int r = idx >> 5, kk = idx & 31;
            aT[kk * 65 + r] = g_A[(m0 + r) * KIN + k0 + kk];
        }
#pragma unroll
        for (int rep = 0; rep < 8; rep++) {
            int idx = rep * 256 + tid;
            int j = idx >> 5, kk = idx & 31;
            int kg = k0 + kk;
            int jg = n0 + j;
            bS[kk * 65 + j] = (kg < 384) ? W_ih[jg * 384 + kg] : W_hh[jg * 256 + (kg - 384)];
        }
        __syncthreads();
#pragma unroll
        for (int kk = 0; kk < 32; kk++) {
            float a[4], w[4];
#pragma unroll
            for (int i = 0; i < 4; i++) a[i] = aT[kk * 65 + ty * 4 + i];
#pragma unroll
            for (int j = 0; j < 4; j++) w[j] = bS[kk * 65 + tx * 4 + j];
#pragma unroll
            for (int i = 0; i < 4; i++)
#pragma unroll
                for (int j = 0; j < 4; j++) acc[i][j] += a[i] * w[j];
        }
    }
#pragma unroll
    for (int i = 0; i < 4; i++) {
        int row = m0 + ty * 4 + i;
#pragma unroll
        for (int j = 0; j < 4; j++) {
            int col = n0 + tx * 4 + j;
            g_gates[row * 1024 + col] = acc[i][j] + b_ih[col] + b_hh[col];
        }
    }
}

// ---------------------------------------------------------------------------
// 3) LSTM cell -> h_t, c_t
// ---------------------------------------------------------------------------
__global__ void cell_kernel(const float* __restrict__ c0, float* __restrict__ out) {
    int b = blockIdx.x, d = threadIdx.x;
    const float* g = g_gates + b * 1024;
    float ig = g[d], fg = g[256 + d], gg = g[512 + d], og = g[768 + d];
    float c = sigmoidf(fg) * c0[b * HH + d] + sigmoidf(ig) * tanhf(gg);
    float h = sigmoidf(og) * tanhf(c);
    out[b * HH + d] = h;
    out[BB * HH + b * HH + d] = c;
}

// ---------------------------------------------------------------------------
// 4) hp = h_t @ W2^T  (256x256, K=256) — tiled GEMM
// ---------------------------------------------------------------------------
__global__ __launch_bounds__(256) void hproj_gemm_kernel(
    const float* __restrict__ W2, const float* __restrict__ out) {
    __shared__ float aT[32 * 65];
    __shared__ float bS[32 * 65];
    int n0 = blockIdx.x * 64;
    int m0 = blockIdx.y * 64;
    int tid = threadIdx.x;
    int tx = tid & 15, ty = tid >> 4;

    float acc[4][4];
#pragma unroll
    for (int i = 0; i < 4; i++)
#pragma unroll
        for (int j = 0; j < 4; j++) acc[i][j] = 0.f;

    for (int k0 = 0; k0 < HH; k0 += 32) {
        __syncthreads();
#pragma unroll
        for (int rep = 0; rep < 8; rep++) {
            int idx = rep * 256 + tid;
            int r = idx >> 5, kk = idx & 31;
            aT[kk * 65 + r] = out[(m0 + r) * HH + k0 + kk];
        }
#pragma unroll
        for (int rep = 0; rep < 8; rep++) {
            int idx = rep * 256 + tid;
            int j = idx >> 5, kk = idx & 31;
            bS[kk * 65 + j] = W2[(n0 + j) * HH + k0 + kk];
        }
        __syncthreads();
#pragma unroll
        for (int kk = 0; kk < 32; kk++) {
            float a[4], w[4];
#pragma unroll
            for (int i = 0; i < 4; i++) a[i] = aT[kk * 65 + ty * 4 + i];
#pragma unroll
            for (int j = 0; j < 4; j++) w[j] = bS[kk * 65 + tx * 4 + j];
#pragma unroll
            for (int i = 0; i < 4; i++)
#pragma unroll
                for (int j = 0; j < 4; j++) acc[i][j] += a[i] * w[j];
        }
    }
#pragma unroll
    for (int i = 0; i < 4; i++)
#pragma unroll
        for (int j = 0; j < 4; j++)
            g_hp[(m0 + ty * 4 + i) * DD + n0 + tx * 4 + j] = acc[i][j];
}

// ---------------------------------------------------------------------------
// 5) PERSISTENT attention (HMMA bf16), 64x64 warp tiles (2m x 4n groups):
//    - enc staged K-permuted -> both A and B fed by single LDS.64
//    - per-warp partial scores, cross-warp combine via sred
//    - split fp32 context pass from gmem (L2-hot)
// ---------------------------------------------------------------------------
__global__ __launch_bounds__(256) void attn_mma_kernel(
    const float* __restrict__ enc, const float* __restrict__ beta) {
    extern __shared__ char sm[];
    float* hpS   = (float*)(sm + SM_HP);
    float* betaS = (float*)(sm + SM_BETA);
    float* wS    = (float*)(sm + SM_WS);
    float* ctxS  = (float*)(sm + SM_CTX);
    float* sred  = (float*)(sm + SM_SRED);
    char*  encS  = sm + SM_ENC;
    char*  w1S   = sm + SM_W1;

    int tid = threadIdx.x, wid = tid >> 5, lane = tid & 31;
    int g = lane >> 2, t = lane & 3;
    int mg = wid >> 2, ng = wid & 3;       // 2 m-groups x 4 n-groups
    int stage_m0 = wid * 16;               // staging rows owned by this warp

    // W1 bf16 (K-permuted) -> smem ONCE: FULL 8448 uint4 (135168 B)
    {
        const uint4* src = (const uint4*)g_W1bf;
        uint4* dst = (uint4*)w1S;
#pragma unroll 4
        for (int it = 0; it < 33; it++) dst[it * 256 + tid] = src[it * 256 + tid];
    }
    betaS[tid] = beta[tid];
    __syncthreads();

    for (int tl = blockIdx.x; tl < BB * NCH; tl += NSM) {
        int b = tl >> 3, ch = tl & 7, l0 = ch << 7;
        const float* encB = enc + ((size_t)b * LL + l0) * DD;

        hpS[tid] = g_hp[b * DD + tid];

        // per-warp enc staging: rows [stage_m0, +16) fp32 -> bf16 K-permuted smem
        {
            const float* wrow = encB + stage_m0 * DD;
            char* sdst = encS + stage_m0 * ROWB;
#pragma unroll 8
            for (int it = 0; it < 32; it++) {
                int idx = it * 32 + lane;       // 1024 float4 per warp
                int rl = idx >> 6;
                int c4 = idx & 63;
                float4 v = *(const float4*)(wrow + rl * DD + c4 * 4);
                __nv_bfloat162 p0 = __floats2bfloat162_rn(v.x, v.y);
                __nv_bfloat162 p1 = __floats2bfloat162_rn(v.z, v.w);
                int k0 = 4 * c4;
                *(uint32_t*)(sdst + rl * ROWB + kperm(k0) * 4)     = *(uint32_t*)&p0;
                *(uint32_t*)(sdst + rl * ROWB + kperm(k0 + 2) * 4) = *(uint32_t*)&p1;
            }
        }
        __syncthreads();   // S0: enc tile + hp complete

        // ---- MMA mainloop: warp tile rows [mg*64,+64) x cols [ng*64,+64)
        float acc[4][8][4];
#pragma unroll
        for (int mi = 0; mi < 4; mi++)
#pragma unroll
            for (int jt = 0; jt < 8; jt++)
#pragma unroll
                for (int i = 0; i < 4; i++) acc[mi][jt][i] = 0.f;

        const char* abase = encS + (mg * 64 + g) * ROWB + t * 8;
        const char* bbase = w1S + (ng * 64 + g) * ROWB + t * 8;
#pragma unroll
        for (int kb = 0; kb < 16; kb++) {
            uint2 alo[4], ahi[4];
#pragma unroll
            for (int mi = 0; mi < 4; mi++) {
                const char* pa = abase + mi * 16 * ROWB + kb * 32;
                alo[mi] = *(const uint2*)(pa);                 // {a0, a2}
                ahi[mi] = *(const uint2*)(pa + 8 * ROWB);      // {a1, a3}
            }
#pragma unroll
            for (int jt = 0; jt < 8; jt++) {
                uint2 bf = *(const uint2*)(bbase + jt * 8 * ROWB + kb * 32);
#pragma unroll
                for (int mi = 0; mi < 4; mi++)
                    mma_bf16(acc[mi][jt], alo[mi].x, ahi[mi].x, alo[mi].y, ahi[mi].y, bf.x, bf.y);
            }
        }

        // ---- epilogue: partial scores over this warp's 64-col range
#pragma unroll
        for (int mi = 0; mi < 4; mi++) {
            float s0 = 0.f, s1 = 0.f;
#pragma unroll
            for (int jt = 0; jt < 8; jt++) {
                int c = ng * 64 + jt * 8 + t * 2;
                float b0 = betaS[c], b1 = betaS[c + 1];
                float h0v = hpS[c], h1v = hpS[c + 1];
                s0 += b0 * tanh_fast(acc[mi][jt][0] + h0v) + b1 * tanh_fast(acc[mi][jt][1] + h1v);
                s1 += b0 * tanh_fast(acc[mi][jt][2] + h0v) + b1 * tanh_fast(acc[mi][jt][3] + h1v);
            }
            s0 += __shfl_xor_sync(0xffffffffu, s0, 1);
            s0 += __shfl_xor_sync(0xffffffffu, s0, 2);
            s1 += __shfl_xor_sync(0xffffffffu, s1, 1);
            s1 += __shfl_xor_sync(0xffffffffu, s1, 2);
            if (t == 0) {
                int row = mg * 64 + mi * 16 + g;
                sred[row * 5 + ng] = s0;
                sred[(row + 8) * 5 + ng] = s1;
            }
        }
        __syncthreads();   // S1: sred complete

        if (tid < 128) {
            float s = sred[tid * 5] + sred[tid * 5 + 1] + sred[tid * 5 + 2] + sred[tid * 5 + 3];
            wS[tid] = expf(s);
        }
        __syncthreads();   // S2: wS complete

        if (tid < 32) {
            float ps = wS[tid] + wS[tid + 32] + wS[tid + 64] + wS[tid + 96];
#pragma unroll
            for (int o = 16; o > 0; o >>= 1) ps += __shfl_down_sync(0xffffffffu, ps, o);
            if (tid == 0) g_partS[b * NCH + ch] = ps;
        }

        // split context pass: group (half) handles 64 rows, fp32, float2 cols
        {
            int p = tid & 127, half = tid >> 7;
            float C0 = 0.f, C1 = 0.f;
            const float* base = encB + (half * 64) * DD + 2 * p;
            const float* wHalf = wS + half * 64;
#pragma unroll 8
            for (int r = 0; r < 64; r++) {
                float2 v = *(const float2*)(base + r * DD);
                float w = wHalf[r];
                C0 += w * v.x;
                C1 += w * v.y;
            }
            if (half) {
                ctxS[2 * p] = C0;
                ctxS[2 * p + 1] = C1;
            }
            __syncthreads();   // S3: ctxS half-1 complete
            if (!half) {
                float* dst = g_partC + (size_t)(b * NCH + ch) * DD;
                dst[2 * p] = C0 + ctxS[2 * p];
                dst[2 * p + 1] = C1 + ctxS[2 * p + 1];
            }
        }
        __syncthreads();   // S4: protect smem before next tile
    }
}

// ---------------------------------------------------------------------------
// 6) context = sum(partC) / sum(partS)
// ---------------------------------------------------------------------------
__global__ void ctx_reduce_kernel() {
    int b = blockIdx.x, d = threadIdx.x;
    float S = 0.f, C = 0.f;
#pragma unroll
    for (int c = 0; c < NCH; c++) {
        S += g_partS[b * NCH + c];
        C += g_partC[(b * NCH + c) * DD + d];
    }
    g_ctx[b * DD + d] = C / S;
}

// ---------------------------------------------------------------------------
// 7) o_new = tanh([h_t | context] @ W3^T)  (256x256, K=512) — tiled
// ---------------------------------------------------------------------------
__global__ __launch_bounds__(256) void onew_gemm_kernel(
    const float* __restrict__ W3, float* __restrict__ out) {
    __shared__ float aT[32 * 65];
    __shared__ float bS[32 * 65];
    int n0 = blockIdx.x * 64;
    int m0 = blockIdx.y * 64;
    int tid = threadIdx.x;
    int tx = tid & 15, ty = tid >> 4;

    float acc[4][4];
#pragma unroll
    for (int i = 0; i < 4; i++)
#pragma unroll
        for (int j = 0; j < 4; j++) acc[i][j] = 0.f;

    for (int k0 = 0; k0 < 512; k0 += 32) {
        __syncthreads();
#pragma unroll
        for (int rep = 0; rep < 8; rep++) {
            int idx = rep * 256 + tid;
            int r = idx >> 5, kk = idx & 31;
            int kg = k0 + kk;
            aT[kk * 65 + r] = (kg < 256) ? out[(m0 + r) * HH + kg]
                                         : g_ctx[(m0 + r) * DD + (kg - 256)];
        }
#pragma unroll
        for (int rep = 0; rep < 8; rep++) {
            int idx = rep * 256 + tid;
            int j = idx >> 5, kk = idx & 31;
            bS[kk * 65 + j] = W3[(n0 + j) * 512 + k0 + kk];
        }
        __syncthreads();
#pragma unroll
        for (int kk = 0; kk < 32; kk++) {
            float a[4], w[4];
#pragma unroll
            for (int i = 0; i < 4; i++) a[i] = aT[kk * 65 + ty * 4 + i];
#pragma unroll
            for (int j = 0; j < 4; j++) w[j] = bS[kk * 65 + tx * 4 + j];
#pragma unroll
            for (int i = 0; i < 4; i++)
#pragma unroll
                for (int j = 0; j < 4; j++) acc[i][j] += a[i] * w[j];
        }
    }
#pragma unroll
    for (int i = 0; i < 4; i++)
#pragma unroll
        for (int j = 0; j < 4; j++)
            out[2 * BB * HH + (m0 + ty * 4 + i) * HH + n0 + tx * 4 + j] = tanhf(acc[i][j]);
}

// ---------------------------------------------------------------------------
// 8) raw logits = o_new @ W_out^T  (256x172, K=256) — tiled
// ---------------------------------------------------------------------------
__global__ __launch_bounds__(256) void logit_gemm_kernel(
    const float* __restrict__ Wout, const float* __restrict__ out) {
    __shared__ float aT[32 * 65];
    __shared__ float bS[32 * 65];
    int n0 = blockIdx.x * 64;
    int m0 = blockIdx.y * 64;
    int tid = threadIdx.x;
    int tx = tid & 15, ty = tid >> 4;
    const float* onew = out + 2 * BB * HH;

    float acc[4][4];
#pragma unroll
    for (int i = 0; i < 4; i++)
#pragma unroll
        for (int j = 0; j < 4; j++) acc[i][j] = 0.f;

    for (int k0 = 0; k0 < HH; k0 += 32) {
        __syncthreads();
#pragma unroll
        for (int rep = 0; rep < 8; rep++) {
            int idx = rep * 256 + tid;
            int r = idx >> 5, kk = idx & 31;
            aT[kk * 65 + r] = onew[(m0 + r) * HH + k0 + kk];
        }
#pragma unroll
        for (int rep = 0; rep < 8; rep++) {
            int idx = rep * 256 + tid;
            int j = idx >> 5, kk = idx & 31;
            int jg = n0 + j;
            bS[kk * 65 + j] = (jg < NOUT) ? Wout[jg * HH + k0 + kk] : 0.f;
        }
        __syncthreads();
#pragma unroll
        for (int kk = 0; kk < 32; kk++) {
            float a[4], w[4];
#pragma unroll
            for (int i = 0; i < 4; i++) a[i] = aT[kk * 65 + ty * 4 + i];
#pragma unroll
            for (int j = 0; j < 4; j++) w[j] = bS[kk * 65 + tx * 4 + j];
#pragma unroll
            for (int i = 0; i < 4; i++)
#pragma unroll
                for (int j = 0; j < 4; j++) acc[i][j] += a[i] * w[j];
        }
    }
#pragma unroll
    for (int i = 0; i < 4; i++) {
        int row = m0 + ty * 4 + i;
#pragma unroll
        for (int j = 0; j < 4; j++) {
            int col = n0 + tx * 4 + j;
            if (col < NOUT) g_logits[row * NOUT + col] = acc[i][j];
        }
    }
}

// ---------------------------------------------------------------------------
// 9) logit softmax
// ---------------------------------------------------------------------------
__global__ void softmax_logit_kernel(float* __restrict__ out) {
    __shared__ float lg[NOUT];
    __shared__ float red;
    int b = blockIdx.x, t = threadIdx.x;
    if (t < NOUT) lg[t] = g_logits[b * NOUT + t];
    __syncthreads();
    if (t == 0) {
        float m = lg[0];
        for (int i = 1; i < NOUT; i++) m = fmaxf(m, lg[i]);
        red = m;
    }
    __syncthreads();
    float e = (t < NOUT) ? expf(lg[t] - red) : 0.f;
    __syncthreads();
    if (t < NOUT) lg[t] = e;
    __syncthreads();
    if (t == 0) {
        float s = 0.f;
        for (int i = 0; i < NOUT; i++) s += lg[i];
        red = s;
    }
    __syncthreads();
    if (t < NOUT) out[3 * BB * HH + b * NOUT + t] = lg[t] / red;
}

// ---------------------------------------------------------------------------
extern "C" void kernel_launch(void* const* d_in, const int* in_sizes, int n_in,
                              void* d_out, int out_size) {
    const float* h0      = (const float*)d_in[0];
    const float* c0      = (const float*)d_in[1];
    const float* o_t     = (const float*)d_in[2];
    const float* enc_out = (const float*)d_in[3];
    const int*   lt      = (const int*)  d_in[4];
    const float* emb     = (const float*)d_in[5];
    const float* W_ih    = (const float*)d_in[6];
    const float* W_hh    = (const float*)d_in[7];
    const float* b_ih    = (const float*)d_in[8];
    const float* b_hh    = (const float*)d_in[9];
    const float* W1      = (const float*)d_in[10];
    const float* W2      = (const float*)d_in[11];
    const float* W3      = (const float*)d_in[12];
    const float* W_out   = (const float*)d_in[13];
    const float* beta    = (const float*)d_in[14];
    float* out = (float*)d_out;

    cudaFuncSetAttribute(attn_mma_kernel, cudaFuncAttributeMaxDynamicSharedMemorySize, SM_TOTAL);

    prep_A_kernel<<<BB, KIN>>>(emb, lt, o_t, h0);
    prep_W1_kernel<<<256, 128>>>(W1);
    gates_gemm_kernel<<<dim3(16, 4), 256>>>(W_ih, W_hh, b_ih, b_hh);
    cell_kernel<<<BB, HH>>>(c0, out);
    hproj_gemm_kernel<<<dim3(4, 4), 256>>>(W2, out);
    attn_mma_kernel<<<NSM, 256, SM_TOTAL>>>(enc_out, beta);
    ctx_reduce_kernel<<<BB, DD>>>();
    onew_gemm_kernel<<<dim3(4, 4), 256>>>(W3, out);
    logit_gemm_kernel<<<dim3(3, 4), 256>>>(W_out, out);
    softmax_logit_kernel<<<BB, 192>>>(out);
}